// round 3
// baseline (speedup 1.0000x reference)
#include <cuda_runtime.h>
#include <cuda_bf16.h>
#include <math.h>

// Problem constants
#define Bq   2
#define Tq   2048
#define Cq   1024
#define Hq   16
#define HDq  64
#define Mq   2048

// Scratch (allocation-free rule: __device__ globals)
__device__ float g_k[Bq * Tq * Cq];   // relu(x @ w1^T + b1)
__device__ float g_v[Bq * Tq * Cq];   // x @ value^T + vb
__device__ float g_y[Bq * Tq * Cq];   // attention output (pre-proj)

// ---------------------------------------------------------------------------
// Dense GEMM: C[M,N] = act(A[M,K] @ W[N,K]^T + bias[N])
// 64x64 block tile, BK=32, 256 threads, 4x4 per-thread microtile.
// ---------------------------------------------------------------------------
template <bool RELU>
__global__ __launch_bounds__(256) void gemm_bias_kernel(
    const float* __restrict__ A, const float* __restrict__ W,
    const float* __restrict__ bias, float* __restrict__ Cmat,
    int Mdim, int Ndim, int Kdim)
{
    const int BM = 64, BN = 64, BK = 32;
    __shared__ float As[BK][BM];
    __shared__ float Bs[BK][BN];

    const int m0 = blockIdx.y * BM;
    const int n0 = blockIdx.x * BN;
    const int tid = threadIdx.x;
    const int tx = tid & 15;        // 0..15 -> 4 cols each
    const int ty = tid >> 4;        // 0..15 -> 4 rows each

    float acc[4][4];
#pragma unroll
    for (int i = 0; i < 4; i++)
#pragma unroll
        for (int j = 0; j < 4; j++) acc[i][j] = 0.f;

    for (int k0 = 0; k0 < Kdim; k0 += BK) {
        // Cooperative loads: 64x32 each, fully coalesced (32 floats per row).
#pragma unroll
        for (int i = 0; i < 8; i++) {
            int flat = tid + i * 256;
            int k = flat & (BK - 1);
            int r = flat / BK;
            As[k][r] = A[(m0 + r) * Kdim + k0 + k];
            Bs[k][r] = W[(n0 + r) * Kdim + k0 + k];
        }
        __syncthreads();

#pragma unroll
        for (int k = 0; k < BK; k++) {
            float a[4], bv[4];
            float4 av = *(const float4*)&As[k][ty * 4];
            float4 bvv = *(const float4*)&Bs[k][tx * 4];
            a[0] = av.x; a[1] = av.y; a[2] = av.z; a[3] = av.w;
            bv[0] = bvv.x; bv[1] = bvv.y; bv[2] = bvv.z; bv[3] = bvv.w;
#pragma unroll
            for (int i = 0; i < 4; i++)
#pragma unroll
                for (int j = 0; j < 4; j++)
                    acc[i][j] += a[i] * bv[j];
        }
        __syncthreads();
    }

    const float4 bq = *(const float4*)&bias[n0 + tx * 4];
    const float bb[4] = {bq.x, bq.y, bq.z, bq.w};
#pragma unroll
    for (int i = 0; i < 4; i++) {
        float4 o;
        float v0 = acc[i][0] + bb[0];
        float v1 = acc[i][1] + bb[1];
        float v2 = acc[i][2] + bb[2];
        float v3 = acc[i][3] + bb[3];
        if (RELU) {
            v0 = fmaxf(v0, 0.f); v1 = fmaxf(v1, 0.f);
            v2 = fmaxf(v2, 0.f); v3 = fmaxf(v3, 0.f);
        }
        o.x = v0; o.y = v1; o.z = v2; o.w = v3;
        *(float4*)&Cmat[(m0 + ty * 4 + i) * Ndim + n0 + tx * 4] = o;
    }
}

// ---------------------------------------------------------------------------
// Fused synthesizer attention:
//   per block: (b, h, 16 query rows)
//   1) load K rows (16x64) to SMEM
//   2) scores S[16 x Lc] = K @ w2[h] + b2 into SMEM (causal Lc = t0+16)
//   3) exact softmax per row in SMEM (cols 0..t)
//   4) out[16x64] = P @ V, streamed from global V
// SMEM: 16*2048 (scores) + 16*64 (K) floats = 132 KB dynamic.
// ---------------------------------------------------------------------------
__global__ __launch_bounds__(256) void attn_kernel(
    const float* __restrict__ gk, const float* __restrict__ gv,
    const float* __restrict__ w2, const float* __restrict__ b2,
    float* __restrict__ gy)
{
    extern __shared__ float sm[];
    float* ps = sm;                  // [16][2048]
    float* ks = sm + 16 * 2048;      // [16][64]

    const int t0 = blockIdx.x * 16;
    const int h  = blockIdx.y;
    const int b  = blockIdx.z;
    const int tid = threadIdx.x;
    const int Lc = t0 + 16;          // columns needed (causal)

    // ---- load K rows ----
#pragma unroll
    for (int i = 0; i < 4; i++) {
        int flat = tid + i * 256;
        int d = flat & 63, r = flat >> 6;
        ks[r * 64 + d] = gk[(b * Tq + t0 + r) * Cq + h * HDq + d];
    }
    __syncthreads();

    // ---- scores: each thread owns one column m per 256-chunk ----
    const float* w2h = w2 + h * HDq * Mq;
    for (int mb = 0; mb < Lc; mb += 256) {
        int m = mb + tid;
        if (m < Lc) {
            float bias = __ldg(&b2[m]);
            float acc[16];
#pragma unroll
            for (int r = 0; r < 16; r++) acc[r] = bias;
#pragma unroll 4
            for (int d4 = 0; d4 < 16; d4++) {
                float w0 = w2h[(d4 * 4 + 0) * Mq + m];
                float w1 = w2h[(d4 * 4 + 1) * Mq + m];
                float w2v = w2h[(d4 * 4 + 2) * Mq + m];
                float w3 = w2h[(d4 * 4 + 3) * Mq + m];
#pragma unroll
                for (int r = 0; r < 16; r++) {
                    float4 kv = *(const float4*)&ks[r * 64 + d4 * 4];
                    acc[r] += kv.x * w0;
                    acc[r] += kv.y * w1;
                    acc[r] += kv.z * w2v;
                    acc[r] += kv.w * w3;
                }
            }
#pragma unroll
            for (int r = 0; r < 16; r++)
                ps[r * 2048 + m] = acc[r];   // masked tail (m>t) never read
        }
    }
    __syncthreads();

    // ---- softmax per row (exact; valid cols 0..t) ----
    {
        const int wid = tid >> 5, lane = tid & 31;
        for (int r = wid; r < 16; r += 8) {
            const int n = t0 + r + 1;
            float* row = ps + r * 2048;
            float mx = -1e30f;
            for (int m = lane; m < n; m += 32) mx = fmaxf(mx, row[m]);
#pragma unroll
            for (int off = 16; off; off >>= 1)
                mx = fmaxf(mx, __shfl_xor_sync(0xffffffffu, mx, off));
            float sum = 0.f;
            for (int m = lane; m < n; m += 32) {
                float e = __expf(row[m] - mx);
                row[m] = e;
                sum += e;
            }
#pragma unroll
            for (int off = 16; off; off >>= 1)
                sum += __shfl_xor_sync(0xffffffffu, sum, off);
            float inv = 1.f / sum;
            for (int m = lane; m < n; m += 32) row[m] *= inv;
        }
    }
    __syncthreads();

    // ---- P @ V: thread = (row r, 4 cols), stream V rows via float4 ----
    {
        const int r = tid >> 4;           // 0..15
        const int c4 = (tid & 15) * 4;    // 0..60
        const int t = t0 + r;
        const int n = t + 1;
        const float* prow = ps + r * 2048;
        const float* vb = gv + b * Tq * Cq + h * HDq + c4;
        float o0 = 0.f, o1 = 0.f, o2 = 0.f, o3 = 0.f;
#pragma unroll 4
        for (int l = 0; l < n; l++) {
            float p = prow[l];
            float4 vv = *(const float4*)&vb[l * Cq];
            o0 += p * vv.x; o1 += p * vv.y; o2 += p * vv.z; o3 += p * vv.w;
        }
        float4 o; o.x = o0; o.y = o1; o.z = o2; o.w = o3;
        *(float4*)&gy[(b * Tq + t) * Cq + h * HDq + c4] = o;
    }
}

// ---------------------------------------------------------------------------
extern "C" void kernel_launch(void* const* d_in, const int* in_sizes, int n_in,
                              void* d_out, int out_size)
{
    const float* x       = (const float*)d_in[0];
    const float* w1_w    = (const float*)d_in[1];
    const float* w1_b    = (const float*)d_in[2];
    const float* w2      = (const float*)d_in[3];
    const float* b2      = (const float*)d_in[4];
    const float* value_w = (const float*)d_in[5];
    const float* value_b = (const float*)d_in[6];
    const float* proj_w  = (const float*)d_in[7];
    const float* proj_b  = (const float*)d_in[8];
    float* out = (float*)d_out;

    float *pk, *pv, *py;
    cudaGetSymbolAddress((void**)&pk, g_k);
    cudaGetSymbolAddress((void**)&pv, g_v);
    cudaGetSymbolAddress((void**)&py, g_y);

    const int SMEM_ATTN = (16 * 2048 + 16 * 64) * (int)sizeof(float);  // 132 KB
    cudaFuncSetAttribute(attn_kernel,
                         cudaFuncAttributeMaxDynamicSharedMemorySize, SMEM_ATTN);

    const int Mrows = Bq * Tq;  // 4096
    dim3 gemm_grid(Cq / 64, Mrows / 64);

    // k = relu(x @ w1^T + b1)
    gemm_bias_kernel<true><<<gemm_grid, 256>>>(x, w1_w, w1_b, pk, Mrows, Cq, Cq);
    // v = x @ value^T + vb
    gemm_bias_kernel<false><<<gemm_grid, 256>>>(x, value_w, value_b, pv, Mrows, Cq, Cq);
    // fused scores + softmax + PV
    dim3 agrid(Tq / 16, Hq, Bq);
    attn_kernel<<<agrid, 256, SMEM_ATTN>>>(pk, pv, w2, b2, py);
    // out = y @ proj^T + pb
    gemm_bias_kernel<false><<<gemm_grid, 256>>>(py, proj_w, proj_b, out, Mrows, Cq, Cq);
}

// round 4
// speedup vs baseline: 2.0773x; 2.0773x over previous
#include <cuda_runtime.h>
#include <cuda_bf16.h>
#include <math.h>

// Problem constants
#define Bq   2
#define Tq   2048
#define Cq   1024
#define Hq   16
#define HDq  64
#define Mq   2048

// Scratch (allocation-free rule: __device__ globals)
__device__ float g_k[Bq * Tq * Cq];   // relu(x @ w1^T + b1)
__device__ float g_v[Bq * Tq * Cq];   // x @ value^T + vb
__device__ float g_y[Bq * Tq * Cq];   // attention output (pre-proj)

// ---------------------------------------------------------------------------
// tf32 helpers
// ---------------------------------------------------------------------------
__device__ __forceinline__ unsigned f2tf32(float x) {
    unsigned u;
    asm("cvt.rna.tf32.f32 %0, %1;" : "=r"(u) : "f"(x));
    return u;
}

__device__ __forceinline__ void mma_tf32(
    float& d0, float& d1, float& d2, float& d3,
    unsigned a0, unsigned a1, unsigned a2, unsigned a3,
    unsigned b0, unsigned b1)
{
    asm volatile(
        "mma.sync.aligned.m16n8k8.row.col.f32.tf32.tf32.f32 "
        "{%0,%1,%2,%3}, {%4,%5,%6,%7}, {%8,%9}, {%0,%1,%2,%3};"
        : "+f"(d0), "+f"(d1), "+f"(d2), "+f"(d3)
        : "r"(a0), "r"(a1), "r"(a2), "r"(a3), "r"(b0), "r"(b1));
}

// ---------------------------------------------------------------------------
// Dense GEMM via 3xTF32 mma.sync:
//   C[M,N] = act(A[M,K] @ W[N,K]^T + bias[N])
// Block tile 128(M) x 64(N) x 16(K), 256 threads = 8 warps (4x2 grid),
// warp tile 32x32 (2 m16-frags x 4 n8-frags). hi/lo split for fp32 accuracy:
//   a*b ~= ah*bh + ah*bl + al*bh   (error ~2^-22, effectively fp32)
// ---------------------------------------------------------------------------
#define GA_PAD 20   // A smem row stride (floats): conflict-free frag reads
#define GB_PAD 72   // B smem row stride

template <bool RELU>
__global__ __launch_bounds__(256) void gemm_tf32_kernel(
    const float* __restrict__ A, const float* __restrict__ W,
    const float* __restrict__ bias, float* __restrict__ Cmat,
    int Mdim, int Ndim, int Kdim)
{
    __shared__ unsigned As_hi[128 * GA_PAD];
    __shared__ unsigned As_lo[128 * GA_PAD];
    __shared__ unsigned Bs_hi[16 * GB_PAD];
    __shared__ unsigned Bs_lo[16 * GB_PAD];

    const int tid  = threadIdx.x;
    const int lane = tid & 31;
    const int wid  = tid >> 5;
    const int wm   = (wid & 3) * 32;   // warp m-offset in block tile
    const int wn   = (wid >> 2) * 32;  // warp n-offset
    const int g    = lane >> 2;        // 0..7
    const int tg   = lane & 3;         // 0..3

    const int m0 = blockIdx.y * 128;
    const int n0 = blockIdx.x * 64;

    // loader indices
    const int lk = tid & 15;           // k within tile
    const int lr = tid >> 4;           // row base (A: +16*i, B(n): +16*i)

    float acc[2][4][4];
#pragma unroll
    for (int im = 0; im < 2; im++)
#pragma unroll
        for (int in = 0; in < 4; in++)
#pragma unroll
            for (int e = 0; e < 4; e++) acc[im][in][e] = 0.f;

    for (int k0 = 0; k0 < Kdim; k0 += 16) {
        // --- load & split A tile 128x16 ---
#pragma unroll
        for (int i = 0; i < 8; i++) {
            int r = lr + i * 16;
            float v = A[(m0 + r) * Kdim + k0 + lk];
            unsigned hi = f2tf32(v);
            float lof = v - __uint_as_float(hi);
            As_hi[r * GA_PAD + lk] = hi;
            As_lo[r * GA_PAD + lk] = f2tf32(lof);
        }
        // --- load & split B tile (Bs[k][n] = W[n0+n][k0+k]) 16x64 ---
#pragma unroll
        for (int i = 0; i < 4; i++) {
            int n = lr + i * 16;
            float v = W[(n0 + n) * Kdim + k0 + lk];
            unsigned hi = f2tf32(v);
            float lof = v - __uint_as_float(hi);
            Bs_hi[lk * GB_PAD + n] = hi;
            Bs_lo[lk * GB_PAD + n] = f2tf32(lof);
        }
        __syncthreads();

#pragma unroll
        for (int ks = 0; ks < 16; ks += 8) {
            unsigned ah[2][4], al[2][4], bh[4][2], bl[4][2];
#pragma unroll
            for (int im = 0; im < 2; im++) {
                int r = wm + im * 16 + g;
                ah[im][0] = As_hi[r * GA_PAD + ks + tg];
                ah[im][1] = As_hi[(r + 8) * GA_PAD + ks + tg];
                ah[im][2] = As_hi[r * GA_PAD + ks + tg + 4];
                ah[im][3] = As_hi[(r + 8) * GA_PAD + ks + tg + 4];
                al[im][0] = As_lo[r * GA_PAD + ks + tg];
                al[im][1] = As_lo[(r + 8) * GA_PAD + ks + tg];
                al[im][2] = As_lo[r * GA_PAD + ks + tg + 4];
                al[im][3] = As_lo[(r + 8) * GA_PAD + ks + tg + 4];
            }
#pragma unroll
            for (int in = 0; in < 4; in++) {
                int c = wn + in * 8 + g;
                bh[in][0] = Bs_hi[(ks + tg) * GB_PAD + c];
                bh[in][1] = Bs_hi[(ks + tg + 4) * GB_PAD + c];
                bl[in][0] = Bs_lo[(ks + tg) * GB_PAD + c];
                bl[in][1] = Bs_lo[(ks + tg + 4) * GB_PAD + c];
            }
#pragma unroll
            for (int im = 0; im < 2; im++)
#pragma unroll
                for (int in = 0; in < 4; in++) {
                    float* d = acc[im][in];
                    mma_tf32(d[0], d[1], d[2], d[3],
                             ah[im][0], ah[im][1], ah[im][2], ah[im][3],
                             bh[in][0], bh[in][1]);
                    mma_tf32(d[0], d[1], d[2], d[3],
                             ah[im][0], ah[im][1], ah[im][2], ah[im][3],
                             bl[in][0], bl[in][1]);
                    mma_tf32(d[0], d[1], d[2], d[3],
                             al[im][0], al[im][1], al[im][2], al[im][3],
                             bh[in][0], bh[in][1]);
                }
        }
        __syncthreads();
    }

    // --- epilogue: bias (+relu), direct global stores (float2 per row-pair) ---
#pragma unroll
    for (int in = 0; in < 4; in++) {
        int col = n0 + wn + in * 8 + 2 * tg;
        float b0 = __ldg(&bias[col]);
        float b1 = __ldg(&bias[col + 1]);
#pragma unroll
        for (int im = 0; im < 2; im++) {
            int row = m0 + wm + im * 16 + g;
            float v0 = acc[im][in][0] + b0;
            float v1 = acc[im][in][1] + b1;
            float v2 = acc[im][in][2] + b0;
            float v3 = acc[im][in][3] + b1;
            if (RELU) {
                v0 = fmaxf(v0, 0.f); v1 = fmaxf(v1, 0.f);
                v2 = fmaxf(v2, 0.f); v3 = fmaxf(v3, 0.f);
            }
            float2 p0; p0.x = v0; p0.y = v1;
            float2 p1; p1.x = v2; p1.y = v3;
            *(float2*)&Cmat[row * Ndim + col] = p0;
            *(float2*)&Cmat[(row + 8) * Ndim + col] = p1;
        }
    }
}

// ---------------------------------------------------------------------------
// Fused synthesizer attention (fp32):
//   per block: (b, h, 16 query rows)
//   1) load K rows (16x64) to SMEM
//   2) scores S[16 x Lc] = K @ w2[h] + b2 into SMEM  (4-col microtile,
//      K values are warp-broadcast LDS reused over 4 cols -> ~79% FMA density)
//   3) exact softmax per row in SMEM (cols 0..t)
//   4) out[16x64] = P @ V, streamed from global V
// ---------------------------------------------------------------------------
__global__ __launch_bounds__(256) void attn_kernel(
    const float* __restrict__ gk, const float* __restrict__ gv,
    const float* __restrict__ w2, const float* __restrict__ b2,
    float* __restrict__ gy)
{
    extern __shared__ float sm[];
    float* ps = sm;                  // [16][2048]
    float* ks = sm + 16 * 2048;      // [16][64]

    const int t0 = blockIdx.x * 16;
    const int h  = blockIdx.y;
    const int b  = blockIdx.z;
    const int tid = threadIdx.x;
    const int Lc = t0 + 16;          // columns needed (causal)

    // ---- load K rows ----
#pragma unroll
    for (int i = 0; i < 4; i++) {
        int flat = tid + i * 256;
        int d = flat & 63, r = flat >> 6;
        ks[r * 64 + d] = gk[(b * Tq + t0 + r) * Cq + h * HDq + d];
    }
    __syncthreads();

    // ---- scores: each thread owns 4 consecutive columns per 1024-chunk ----
    const float* w2h = w2 + h * HDq * Mq;
    for (int mb = 0; mb < Lc; mb += 1024) {
        int m = mb + (tid << 2);
        if (m < Lc) {
            float4 bb = *(const float4*)&b2[m];
            float a0[16], a1[16], a2[16], a3[16];
#pragma unroll
            for (int r = 0; r < 16; r++) {
                a0[r] = bb.x; a1[r] = bb.y; a2[r] = bb.z; a3[r] = bb.w;
            }
#pragma unroll 8
            for (int d = 0; d < 64; d++) {
                float4 w = *(const float4*)&w2h[d * Mq + m];
#pragma unroll
                for (int r = 0; r < 16; r++) {
                    float kv = ks[r * 64 + d];    // warp-uniform -> broadcast
                    a0[r] += kv * w.x;
                    a1[r] += kv * w.y;
                    a2[r] += kv * w.z;
                    a3[r] += kv * w.w;
                }
            }
#pragma unroll
            for (int r = 0; r < 16; r++) {
                float4 o; o.x = a0[r]; o.y = a1[r]; o.z = a2[r]; o.w = a3[r];
                *(float4*)&ps[r * 2048 + m] = o;   // masked tail never read
            }
        }
    }
    __syncthreads();

    // ---- softmax per row (exact; valid cols 0..t) ----
    {
        const int wid = tid >> 5, lane = tid & 31;
        for (int r = wid; r < 16; r += 8) {
            const int n = t0 + r + 1;
            float* row = ps + r * 2048;
            float mx = -1e30f;
            for (int m = lane; m < n; m += 32) mx = fmaxf(mx, row[m]);
#pragma unroll
            for (int off = 16; off; off >>= 1)
                mx = fmaxf(mx, __shfl_xor_sync(0xffffffffu, mx, off));
            float sum = 0.f;
            for (int m = lane; m < n; m += 32) {
                float e = __expf(row[m] - mx);
                row[m] = e;
                sum += e;
            }
#pragma unroll
            for (int off = 16; off; off >>= 1)
                sum += __shfl_xor_sync(0xffffffffu, sum, off);
            float inv = 1.f / sum;
            for (int m = lane; m < n; m += 32) row[m] *= inv;
        }
    }
    __syncthreads();

    // ---- P @ V: thread = (row r, 4 cols), stream V rows via float4 ----
    {
        const int r = tid >> 4;           // 0..15
        const int c4 = (tid & 15) * 4;    // 0..60
        const int t = t0 + r;
        const int n = t + 1;
        const float* prow = ps + r * 2048;
        const float* vb = gv + b * Tq * Cq + h * HDq + c4;
        float o0 = 0.f, o1 = 0.f, o2 = 0.f, o3 = 0.f;
#pragma unroll 8
        for (int l = 0; l < n; l++) {
            float p = prow[l];
            float4 vv = *(const float4*)&vb[l * Cq];
            o0 += p * vv.x; o1 += p * vv.y; o2 += p * vv.z; o3 += p * vv.w;
        }
        float4 o; o.x = o0; o.y = o1; o.z = o2; o.w = o3;
        *(float4*)&gy[(b * Tq + t) * Cq + h * HDq + c4] = o;
    }
}

// ---------------------------------------------------------------------------
extern "C" void kernel_launch(void* const* d_in, const int* in_sizes, int n_in,
                              void* d_out, int out_size)
{
    const float* x       = (const float*)d_in[0];
    const float* w1_w    = (const float*)d_in[1];
    const float* w1_b    = (const float*)d_in[2];
    const float* w2      = (const float*)d_in[3];
    const float* b2      = (const float*)d_in[4];
    const float* value_w = (const float*)d_in[5];
    const float* value_b = (const float*)d_in[6];
    const float* proj_w  = (const float*)d_in[7];
    const float* proj_b  = (const float*)d_in[8];
    float* out = (float*)d_out;

    float *pk, *pv, *py;
    cudaGetSymbolAddress((void**)&pk, g_k);
    cudaGetSymbolAddress((void**)&pv, g_v);
    cudaGetSymbolAddress((void**)&py, g_y);

    const int SMEM_ATTN = (16 * 2048 + 16 * 64) * (int)sizeof(float);  // 132 KB
    cudaFuncSetAttribute(attn_kernel,
                         cudaFuncAttributeMaxDynamicSharedMemorySize, SMEM_ATTN);

    const int Mrows = Bq * Tq;  // 4096
    dim3 gemm_grid(Cq / 64, Mrows / 128);  // (16, 32)

    // k = relu(x @ w1^T + b1)
    gemm_tf32_kernel<true><<<gemm_grid, 256>>>(x, w1_w, w1_b, pk, Mrows, Cq, Cq);
    // v = x @ value^T + vb
    gemm_tf32_kernel<false><<<gemm_grid, 256>>>(x, value_w, value_b, pv, Mrows, Cq, Cq);
    // fused scores + softmax + PV
    dim3 agrid(Tq / 16, Hq, Bq);
    attn_kernel<<<agrid, 256, SMEM_ATTN>>>(pk, pv, w2, b2, py);
    // out = y @ proj^T + pb
    gemm_tf32_kernel<false><<<gemm_grid, 256>>>(py, proj_w, proj_b, out, Mrows, Cq, Cq);
}

// round 5
// speedup vs baseline: 3.3548x; 1.6150x over previous
#include <cuda_runtime.h>
#include <cuda_bf16.h>
#include <math.h>

// Problem constants
#define Bq   2
#define Tq   2048
#define Cq   1024
#define Hq   16
#define HDq  64
#define Mq   2048

// Scratch (allocation-free rule: __device__ globals)
__device__ float g_k[Bq * Tq * Cq];   // relu(x @ w1^T + b1)
__device__ float g_v[Bq * Tq * Cq];   // x @ value^T + vb
__device__ float g_y[Bq * Tq * Cq];   // attention output (pre-proj)

// ---------------------------------------------------------------------------
// tf32 helpers
// ---------------------------------------------------------------------------
__device__ __forceinline__ unsigned f2tf32(float x) {
    unsigned u;
    asm("cvt.rna.tf32.f32 %0, %1;" : "=r"(u) : "f"(x));
    return u;
}

__device__ __forceinline__ void mma_tf32(
    float& d0, float& d1, float& d2, float& d3,
    unsigned a0, unsigned a1, unsigned a2, unsigned a3,
    unsigned b0, unsigned b1)
{
    asm volatile(
        "mma.sync.aligned.m16n8k8.row.col.f32.tf32.tf32.f32 "
        "{%0,%1,%2,%3}, {%4,%5,%6,%7}, {%8,%9}, {%0,%1,%2,%3};"
        : "+f"(d0), "+f"(d1), "+f"(d2), "+f"(d3)
        : "r"(a0), "r"(a1), "r"(a2), "r"(a3), "r"(b0), "r"(b1));
}

// ---------------------------------------------------------------------------
// Dense GEMM via 3xTF32 mma.sync (validated R4): C = act(A @ W^T + bias)
// ---------------------------------------------------------------------------
#define GA_PAD 20
#define GB_PAD 72

template <bool RELU>
__global__ __launch_bounds__(256) void gemm_tf32_kernel(
    const float* __restrict__ A, const float* __restrict__ W,
    const float* __restrict__ bias, float* __restrict__ Cmat,
    int Mdim, int Ndim, int Kdim)
{
    __shared__ unsigned As_hi[128 * GA_PAD];
    __shared__ unsigned As_lo[128 * GA_PAD];
    __shared__ unsigned Bs_hi[16 * GB_PAD];
    __shared__ unsigned Bs_lo[16 * GB_PAD];

    const int tid  = threadIdx.x;
    const int lane = tid & 31;
    const int wid  = tid >> 5;
    const int wm   = (wid & 3) * 32;
    const int wn   = (wid >> 2) * 32;
    const int g    = lane >> 2;
    const int tg   = lane & 3;

    const int m0 = blockIdx.y * 128;
    const int n0 = blockIdx.x * 64;

    const int lk = tid & 15;
    const int lr = tid >> 4;

    float acc[2][4][4];
#pragma unroll
    for (int im = 0; im < 2; im++)
#pragma unroll
        for (int in = 0; in < 4; in++)
#pragma unroll
            for (int e = 0; e < 4; e++) acc[im][in][e] = 0.f;

    for (int k0 = 0; k0 < Kdim; k0 += 16) {
#pragma unroll
        for (int i = 0; i < 8; i++) {
            int r = lr + i * 16;
            float v = A[(m0 + r) * Kdim + k0 + lk];
            unsigned hi = f2tf32(v);
            float lof = v - __uint_as_float(hi);
            As_hi[r * GA_PAD + lk] = hi;
            As_lo[r * GA_PAD + lk] = f2tf32(lof);
        }
#pragma unroll
        for (int i = 0; i < 4; i++) {
            int n = lr + i * 16;
            float v = W[(n0 + n) * Kdim + k0 + lk];
            unsigned hi = f2tf32(v);
            float lof = v - __uint_as_float(hi);
            Bs_hi[lk * GB_PAD + n] = hi;
            Bs_lo[lk * GB_PAD + n] = f2tf32(lof);
        }
        __syncthreads();

#pragma unroll
        for (int ks = 0; ks < 16; ks += 8) {
            unsigned ah[2][4], al[2][4], bh[4][2], bl[4][2];
#pragma unroll
            for (int im = 0; im < 2; im++) {
                int r = wm + im * 16 + g;
                ah[im][0] = As_hi[r * GA_PAD + ks + tg];
                ah[im][1] = As_hi[(r + 8) * GA_PAD + ks + tg];
                ah[im][2] = As_hi[r * GA_PAD + ks + tg + 4];
                ah[im][3] = As_hi[(r + 8) * GA_PAD + ks + tg + 4];
                al[im][0] = As_lo[r * GA_PAD + ks + tg];
                al[im][1] = As_lo[(r + 8) * GA_PAD + ks + tg];
                al[im][2] = As_lo[r * GA_PAD + ks + tg + 4];
                al[im][3] = As_lo[(r + 8) * GA_PAD + ks + tg + 4];
            }
#pragma unroll
            for (int in = 0; in < 4; in++) {
                int c = wn + in * 8 + g;
                bh[in][0] = Bs_hi[(ks + tg) * GB_PAD + c];
                bh[in][1] = Bs_hi[(ks + tg + 4) * GB_PAD + c];
                bl[in][0] = Bs_lo[(ks + tg) * GB_PAD + c];
                bl[in][1] = Bs_lo[(ks + tg + 4) * GB_PAD + c];
            }
#pragma unroll
            for (int im = 0; im < 2; im++)
#pragma unroll
                for (int in = 0; in < 4; in++) {
                    float* d = acc[im][in];
                    mma_tf32(d[0], d[1], d[2], d[3],
                             ah[im][0], ah[im][1], ah[im][2], ah[im][3],
                             bh[in][0], bh[in][1]);
                    mma_tf32(d[0], d[1], d[2], d[3],
                             ah[im][0], ah[im][1], ah[im][2], ah[im][3],
                             bl[in][0], bl[in][1]);
                    mma_tf32(d[0], d[1], d[2], d[3],
                             al[im][0], al[im][1], al[im][2], al[im][3],
                             bh[in][0], bh[in][1]);
                }
        }
        __syncthreads();
    }

#pragma unroll
    for (int in = 0; in < 4; in++) {
        int col = n0 + wn + in * 8 + 2 * tg;
        float b0 = __ldg(&bias[col]);
        float b1 = __ldg(&bias[col + 1]);
#pragma unroll
        for (int im = 0; im < 2; im++) {
            int row = m0 + wm + im * 16 + g;
            float v0 = acc[im][in][0] + b0;
            float v1 = acc[im][in][1] + b1;
            float v2 = acc[im][in][2] + b0;
            float v3 = acc[im][in][3] + b1;
            if (RELU) {
                v0 = fmaxf(v0, 0.f); v1 = fmaxf(v1, 0.f);
                v2 = fmaxf(v2, 0.f); v3 = fmaxf(v3, 0.f);
            }
            float2 p0; p0.x = v0; p0.y = v1;
            float2 p1; p1.x = v2; p1.y = v3;
            *(float2*)&Cmat[row * Ndim + col] = p0;
            *(float2*)&Cmat[(row + 8) * Ndim + col] = p1;
        }
    }
}

// ---------------------------------------------------------------------------
// Fused synthesizer attention, fully tensorized (tf32 mma, single-pass):
//   per block (b, h, 16 query rows):
//   1) K rows (16x64) -> smem, preconverted to 8 A-fragments in registers
//   2) scores S = K @ w2[h] + b2 via mma, B-frags ldg'd from L2 (2-chain ILP)
//   3) softmax: no max-pass (|logit| < 1), exp + sum, zero masked tail,
//      1/sum deferred to PV epilogue
//   4) out = P @ V via mma (P A-frags from padded smem, V B-frags from L2),
//      scaled by row inv-sum in epilogue
// smem: ps[16][2052] + ks[16][68] + sinv[16] ~ 132.7 KB
// ---------------------------------------------------------------------------
#define PS  2052   // ps row stride: bank = (4g+tg+l0)%32 -> conflict-free frags
#define KSP 68     // ks row stride, same trick

__global__ __launch_bounds__(256) void attn_kernel(
    const float* __restrict__ gk, const float* __restrict__ gv,
    const float* __restrict__ w2, const float* __restrict__ b2,
    float* __restrict__ gy)
{
    extern __shared__ float sm[];
    float* ps   = sm;                    // [16][PS]
    float* ks   = sm + 16 * PS;          // [16][KSP]
    float* sinv = ks + 16 * KSP;         // [16]

    const int t0  = blockIdx.x * 16;
    const int h   = blockIdx.y;
    const int b   = blockIdx.z;
    const int tid = threadIdx.x;
    const int lane = tid & 31;
    const int wid  = tid >> 5;           // 0..7
    const int g    = lane >> 2;          // 0..7
    const int tg   = lane & 3;           // 0..3
    const int Lc   = t0 + 16;            // causal column count (mult of 16)

    // ---- load K rows (16x64) ----
#pragma unroll
    for (int i = 0; i < 4; i++) {
        int flat = tid + i * 256;
        int d = flat & 63, r = flat >> 6;
        ks[r * KSP + d] = gk[(b * Tq + t0 + r) * Cq + h * HDq + d];
    }
    __syncthreads();

    // ---- preload A fragments: K[16x64] as 8 k-frags (all warps identical) ----
    unsigned A0[8], A1[8], A2[8], A3[8];
#pragma unroll
    for (int kf = 0; kf < 8; kf++) {
        A0[kf] = f2tf32(ks[g * KSP + kf * 8 + tg]);
        A1[kf] = f2tf32(ks[(g + 8) * KSP + kf * 8 + tg]);
        A2[kf] = f2tf32(ks[g * KSP + kf * 8 + tg + 4]);
        A3[kf] = f2tf32(ks[(g + 8) * KSP + kf * 8 + tg + 4]);
    }

    // ---- score phase: warp w owns column stripes w*8 + 64*j; 2-group ILP ----
    const float* w2h = w2 + h * HDq * Mq;
    for (int n0 = wid * 8; n0 < Lc; n0 += 128) {
        const int n1 = n0 + 64;
        const bool go1 = (n1 < Lc);
        float d0[4] = {0.f, 0.f, 0.f, 0.f};
        float d1[4] = {0.f, 0.f, 0.f, 0.f};
#pragma unroll
        for (int kf = 0; kf < 8; kf++) {
            const int r0 = (kf * 8 + tg) * Mq;
            const int r4 = (kf * 8 + tg + 4) * Mq;
            unsigned b00 = f2tf32(__ldg(&w2h[r0 + n0 + g]));
            unsigned b01 = f2tf32(__ldg(&w2h[r4 + n0 + g]));
            mma_tf32(d0[0], d0[1], d0[2], d0[3],
                     A0[kf], A1[kf], A2[kf], A3[kf], b00, b01);
            if (go1) {
                unsigned b10 = f2tf32(__ldg(&w2h[r0 + n1 + g]));
                unsigned b11 = f2tf32(__ldg(&w2h[r4 + n1 + g]));
                mma_tf32(d1[0], d1[1], d1[2], d1[3],
                         A0[kf], A1[kf], A2[kf], A3[kf], b10, b11);
            }
        }
        {
            float2 bz = *(const float2*)&b2[n0 + 2 * tg];
            float2 p0; p0.x = d0[0] + bz.x; p0.y = d0[1] + bz.y;
            float2 p1; p1.x = d0[2] + bz.x; p1.y = d0[3] + bz.y;
            *(float2*)&ps[g * PS + n0 + 2 * tg] = p0;
            *(float2*)&ps[(g + 8) * PS + n0 + 2 * tg] = p1;
        }
        if (go1) {
            float2 bz = *(const float2*)&b2[n1 + 2 * tg];
            float2 p0; p0.x = d1[0] + bz.x; p0.y = d1[1] + bz.y;
            float2 p1; p1.x = d1[2] + bz.x; p1.y = d1[3] + bz.y;
            *(float2*)&ps[g * PS + n1 + 2 * tg] = p0;
            *(float2*)&ps[(g + 8) * PS + n1 + 2 * tg] = p1;
        }
    }
    __syncthreads();

    // ---- softmax (no max subtraction: |logit| << 1). Zero masked tail. ----
    for (int r = wid; r < 16; r += 8) {
        const int n = t0 + r + 1;
        float* row = ps + r * PS;
        float sum = 0.f;
        for (int m = lane; m < n; m += 32) {
            float e = __expf(row[m]);
            row[m] = e;
            sum += e;
        }
#pragma unroll
        for (int off = 16; off; off >>= 1)
            sum += __shfl_xor_sync(0xffffffffu, sum, off);
        if (lane == 0) sinv[r] = 1.f / sum;
        // zero masked cols [n, Lc) so PV's full-width sweep is exact
        for (int m = n + lane; m < Lc; m += 32) row[m] = 0.f;
    }
    __syncthreads();

    // ---- PV: warp w owns out cols [8w, 8w+8); accumulate over Lc (2 chains) ----
    {
        const int c0 = wid * 8;
        const float* vb = gv + (long)(b * Tq) * Cq + h * HDq + c0 + g;
        float e0[4] = {0.f, 0.f, 0.f, 0.f};
        float e1[4] = {0.f, 0.f, 0.f, 0.f};
        const int nk = Lc >> 3;          // even (Lc mult of 16)
        for (int kf = 0; kf < nk; kf += 2) {
            const int l0 = kf * 8;
            const int l1 = l0 + 8;
            unsigned a0 = f2tf32(ps[g * PS + l0 + tg]);
            unsigned a1 = f2tf32(ps[(g + 8) * PS + l0 + tg]);
            unsigned a2 = f2tf32(ps[g * PS + l0 + tg + 4]);
            unsigned a3 = f2tf32(ps[(g + 8) * PS + l0 + tg + 4]);
            unsigned b0 = f2tf32(__ldg(&vb[(l0 + tg) * Cq]));
            unsigned b1 = f2tf32(__ldg(&vb[(l0 + tg + 4) * Cq]));
            mma_tf32(e0[0], e0[1], e0[2], e0[3], a0, a1, a2, a3, b0, b1);
            unsigned c0r = f2tf32(ps[g * PS + l1 + tg]);
            unsigned c1r = f2tf32(ps[(g + 8) * PS + l1 + tg]);
            unsigned c2r = f2tf32(ps[g * PS + l1 + tg + 4]);
            unsigned c3r = f2tf32(ps[(g + 8) * PS + l1 + tg + 4]);
            unsigned d0r = f2tf32(__ldg(&vb[(l1 + tg) * Cq]));
            unsigned d1r = f2tf32(__ldg(&vb[(l1 + tg + 4) * Cq]));
            mma_tf32(e1[0], e1[1], e1[2], e1[3], c0r, c1r, c2r, c3r, d0r, d1r);
        }
        const float ivg = sinv[g];
        const float ivh = sinv[g + 8];
        float2 o0, o1;
        o0.x = (e0[0] + e1[0]) * ivg;
        o0.y = (e0[1] + e1[1]) * ivg;
        o1.x = (e0[2] + e1[2]) * ivh;
        o1.y = (e0[3] + e1[3]) * ivh;
        float* gy0 = gy + (long)(b * Tq + t0 + g) * Cq + h * HDq + c0 + 2 * tg;
        float* gy1 = gy + (long)(b * Tq + t0 + g + 8) * Cq + h * HDq + c0 + 2 * tg;
        *(float2*)gy0 = o0;
        *(float2*)gy1 = o1;
    }
}

// ---------------------------------------------------------------------------
extern "C" void kernel_launch(void* const* d_in, const int* in_sizes, int n_in,
                              void* d_out, int out_size)
{
    const float* x       = (const float*)d_in[0];
    const float* w1_w    = (const float*)d_in[1];
    const float* w1_b    = (const float*)d_in[2];
    const float* w2      = (const float*)d_in[3];
    const float* b2      = (const float*)d_in[4];
    const float* value_w = (const float*)d_in[5];
    const float* value_b = (const float*)d_in[6];
    const float* proj_w  = (const float*)d_in[7];
    const float* proj_b  = (const float*)d_in[8];
    float* out = (float*)d_out;

    float *pk, *pv, *py;
    cudaGetSymbolAddress((void**)&pk, g_k);
    cudaGetSymbolAddress((void**)&pv, g_v);
    cudaGetSymbolAddress((void**)&py, g_y);

    const int SMEM_ATTN = (16 * PS + 16 * KSP + 16) * (int)sizeof(float);
    cudaFuncSetAttribute(attn_kernel,
                         cudaFuncAttributeMaxDynamicSharedMemorySize, SMEM_ATTN);

    const int Mrows = Bq * Tq;  // 4096
    dim3 gemm_grid(Cq / 64, Mrows / 128);  // (16, 32)

    gemm_tf32_kernel<true><<<gemm_grid, 256>>>(x, w1_w, w1_b, pk, Mrows, Cq, Cq);
    gemm_tf32_kernel<false><<<gemm_grid, 256>>>(x, value_w, value_b, pv, Mrows, Cq, Cq);
    dim3 agrid(Tq / 16, Hq, Bq);
    attn_kernel<<<agrid, 256, SMEM_ATTN>>>(pk, pv, w2, b2, py);
    gemm_tf32_kernel<false><<<gemm_grid, 256>>>(py, proj_w, proj_b, out, Mrows, Cq, Cq);
}

// round 6
// speedup vs baseline: 3.6649x; 1.0925x over previous
#include <cuda_runtime.h>
#include <cuda_bf16.h>
#include <math.h>

// Problem constants
#define Bq   2
#define Tq   2048
#define Cq   1024
#define Hq   16
#define HDq  64
#define Mq   2048

// Scratch (allocation-free rule: __device__ globals)
__device__ float    g_k[Bq * Tq * Cq];     // relu(x @ w1^T + b1), tf32-rounded
__device__ float    g_v[Bq * Tq * Cq];     // x @ value^T + vb, tf32-rounded
__device__ float    g_y[Bq * Tq * Cq];     // attention output (pre-proj, fp32)
__device__ unsigned g_ahi[Bq * Tq * Cq];   // activation hi plane (x, then y)
__device__ unsigned g_alo[Bq * Tq * Cq];   // activation lo plane
__device__ unsigned g_whi[Cq * Cq];        // weight hi plane (per-GEMM reuse)
__device__ unsigned g_wlo[Cq * Cq];        // weight lo plane
__device__ float    g_w2r[Hq * HDq * Mq];  // w2 tf32-rounded

// ---------------------------------------------------------------------------
// tf32 / async helpers
// ---------------------------------------------------------------------------
__device__ __forceinline__ unsigned f2tf32(float x) {
    unsigned u;
    asm("cvt.rna.tf32.f32 %0, %1;" : "=r"(u) : "f"(x));
    return u;
}

__device__ __forceinline__ void mma_tf32(
    float& d0, float& d1, float& d2, float& d3,
    unsigned a0, unsigned a1, unsigned a2, unsigned a3,
    unsigned b0, unsigned b1)
{
    asm volatile(
        "mma.sync.aligned.m16n8k8.row.col.f32.tf32.tf32.f32 "
        "{%0,%1,%2,%3}, {%4,%5,%6,%7}, {%8,%9}, {%0,%1,%2,%3};"
        : "+f"(d0), "+f"(d1), "+f"(d2), "+f"(d3)
        : "r"(a0), "r"(a1), "r"(a2), "r"(a3), "r"(b0), "r"(b1));
}

__device__ __forceinline__ void cp_async16(void* s, const void* g) {
    unsigned sa = (unsigned)__cvta_generic_to_shared(s);
    asm volatile("cp.async.cg.shared.global [%0], [%1], 16;" :: "r"(sa), "l"(g));
}

// ---------------------------------------------------------------------------
// Prep kernels: hi/lo split (a ~= hi + lo, both tf32) and tf32 rounding
// ---------------------------------------------------------------------------
__global__ __launch_bounds__(256) void split_kernel(
    const float4* __restrict__ in, uint4* __restrict__ hi,
    uint4* __restrict__ lo, int n4)
{
    int i = blockIdx.x * 256 + threadIdx.x;
    if (i < n4) {
        float4 v = in[i];
        uint4 h, l;
        h.x = f2tf32(v.x); l.x = f2tf32(v.x - __uint_as_float(h.x));
        h.y = f2tf32(v.y); l.y = f2tf32(v.y - __uint_as_float(h.y));
        h.z = f2tf32(v.z); l.z = f2tf32(v.z - __uint_as_float(h.z));
        h.w = f2tf32(v.w); l.w = f2tf32(v.w - __uint_as_float(h.w));
        hi[i] = h; lo[i] = l;
    }
}

__global__ __launch_bounds__(256) void round_kernel(
    const float4* __restrict__ in, float4* __restrict__ out, int n4)
{
    int i = blockIdx.x * 256 + threadIdx.x;
    if (i < n4) {
        float4 v = in[i];
        float4 o;
        o.x = __uint_as_float(f2tf32(v.x));
        o.y = __uint_as_float(f2tf32(v.y));
        o.z = __uint_as_float(f2tf32(v.z));
        o.w = __uint_as_float(f2tf32(v.w));
        out[i] = o;
    }
}

// ---------------------------------------------------------------------------
// Dense GEMM, pre-split operands, cp.async 2-stage pipeline, 3xTF32 mma:
//   C[M,N] = act(A[M,K] @ W[N,K]^T + bias[N])
// Block 128x128x16, 8 warps (4m x 2n), warp tile 32x64.
// smem: 4 planes x 2 stages x 128 rows x stride 20 = 80 KB dynamic.
// ---------------------------------------------------------------------------
#define ST   20     // smem row stride (words): conflict-free fragment reads
#define PLW  2560   // words per plane-stage (128*ST)

template <bool RELU, bool ROUND_OUT>
__global__ __launch_bounds__(256) void gemm_ds_kernel(
    const unsigned* __restrict__ Ahi, const unsigned* __restrict__ Alo,
    const unsigned* __restrict__ Whi, const unsigned* __restrict__ Wlo,
    const float* __restrict__ bias, float* __restrict__ Cmat,
    int Mdim, int Ndim, int Kdim)
{
    extern __shared__ unsigned smu[];
    unsigned* sAh = smu;                 // [2][PLW]
    unsigned* sAl = sAh + 2 * PLW;
    unsigned* sBh = sAl + 2 * PLW;
    unsigned* sBl = sBh + 2 * PLW;

    const int tid  = threadIdx.x;
    const int lane = tid & 31;
    const int wid  = tid >> 5;
    const int wm   = (wid & 3) * 32;     // warp m-offset
    const int wn   = (wid >> 2) * 64;    // warp n-offset
    const int g    = lane >> 2;
    const int tg   = lane & 3;

    const int m0 = blockIdx.y * 128;
    const int n0 = blockIdx.x * 128;
    const int NK = Kdim >> 4;

    // loader geometry: 2048 16B-chunks per stage, 8 per thread.
    // i>>1 selects plane (Ahi,Alo,Whi,Wlo); (tid + (i&1)*256) -> row/k4.
    const int lrow = ((tid & 255) + 0) >> 2;      // placeholder; computed per i
    (void)lrow;

    float acc[2][8][4];
#pragma unroll
    for (int im = 0; im < 2; im++)
#pragma unroll
        for (int in = 0; in < 8; in++)
#pragma unroll
            for (int e = 0; e < 4; e++) acc[im][in][e] = 0.f;

    auto load_stage = [&](int kt, int st) {
        const int k0 = kt << 4;
#pragma unroll
        for (int i = 0; i < 8; i++) {
            int cc = tid + (i & 1) * 256;   // 0..511
            int r  = cc >> 2;               // 0..127
            int k4 = (cc & 3) << 2;
            if ((i >> 1) == 0)
                cp_async16(&sAh[st * PLW + r * ST + k4],
                           &Ahi[(size_t)(m0 + r) * Kdim + k0 + k4]);
            else if ((i >> 1) == 1)
                cp_async16(&sAl[st * PLW + r * ST + k4],
                           &Alo[(size_t)(m0 + r) * Kdim + k0 + k4]);
            else if ((i >> 1) == 2)
                cp_async16(&sBh[st * PLW + r * ST + k4],
                           &Whi[(size_t)(n0 + r) * Kdim + k0 + k4]);
            else
                cp_async16(&sBl[st * PLW + r * ST + k4],
                           &Wlo[(size_t)(n0 + r) * Kdim + k0 + k4]);
        }
        asm volatile("cp.async.commit_group;" ::: "memory");
    };

    load_stage(0, 0);

    for (int kt = 0; kt < NK; kt++) {
        const int cur = kt & 1;
        if (kt + 1 < NK) {
            load_stage(kt + 1, (kt + 1) & 1);
            asm volatile("cp.async.wait_group 1;" ::: "memory");
        } else {
            asm volatile("cp.async.wait_group 0;" ::: "memory");
        }
        __syncthreads();

        const unsigned* pAh = sAh + cur * PLW;
        const unsigned* pAl = sAl + cur * PLW;
        const unsigned* pBh = sBh + cur * PLW;
        const unsigned* pBl = sBl + cur * PLW;

#pragma unroll
        for (int ks = 0; ks < 16; ks += 8) {
            unsigned ah[2][4], al[2][4], bh[8][2], bl[8][2];
#pragma unroll
            for (int im = 0; im < 2; im++) {
                int r = wm + im * 16 + g;
                ah[im][0] = pAh[r * ST + ks + tg];
                ah[im][1] = pAh[(r + 8) * ST + ks + tg];
                ah[im][2] = pAh[r * ST + ks + tg + 4];
                ah[im][3] = pAh[(r + 8) * ST + ks + tg + 4];
                al[im][0] = pAl[r * ST + ks + tg];
                al[im][1] = pAl[(r + 8) * ST + ks + tg];
                al[im][2] = pAl[r * ST + ks + tg + 4];
                al[im][3] = pAl[(r + 8) * ST + ks + tg + 4];
            }
#pragma unroll
            for (int in = 0; in < 8; in++) {
                int c = wn + in * 8 + g;
                bh[in][0] = pBh[c * ST + ks + tg];
                bh[in][1] = pBh[c * ST + ks + tg + 4];
                bl[in][0] = pBl[c * ST + ks + tg];
                bl[in][1] = pBl[c * ST + ks + tg + 4];
            }
#pragma unroll
            for (int im = 0; im < 2; im++)
#pragma unroll
                for (int in = 0; in < 8; in++) {
                    float* d = acc[im][in];
                    mma_tf32(d[0], d[1], d[2], d[3],
                             ah[im][0], ah[im][1], ah[im][2], ah[im][3],
                             bh[in][0], bh[in][1]);
                    mma_tf32(d[0], d[1], d[2], d[3],
                             ah[im][0], ah[im][1], ah[im][2], ah[im][3],
                             bl[in][0], bl[in][1]);
                    mma_tf32(d[0], d[1], d[2], d[3],
                             al[im][0], al[im][1], al[im][2], al[im][3],
                             bh[in][0], bh[in][1]);
                }
        }
        __syncthreads();
    }

    // epilogue: bias (+relu) (+tf32 round), direct float2 stores
#pragma unroll
    for (int in = 0; in < 8; in++) {
        int col = n0 + wn + in * 8 + 2 * tg;
        float2 bz = *(const float2*)&bias[col];
#pragma unroll
        for (int im = 0; im < 2; im++) {
            int row = m0 + wm + im * 16 + g;
            float v0 = acc[im][in][0] + bz.x;
            float v1 = acc[im][in][1] + bz.y;
            float v2 = acc[im][in][2] + bz.x;
            float v3 = acc[im][in][3] + bz.y;
            if (RELU) {
                v0 = fmaxf(v0, 0.f); v1 = fmaxf(v1, 0.f);
                v2 = fmaxf(v2, 0.f); v3 = fmaxf(v3, 0.f);
            }
            if (ROUND_OUT) {
                v0 = __uint_as_float(f2tf32(v0));
                v1 = __uint_as_float(f2tf32(v1));
                v2 = __uint_as_float(f2tf32(v2));
                v3 = __uint_as_float(f2tf32(v3));
            }
            float2 p0; p0.x = v0; p0.y = v1;
            float2 p1; p1.x = v2; p1.y = v3;
            *(float2*)&Cmat[(size_t)row * Ndim + col] = p0;
            *(float2*)&Cmat[(size_t)(row + 8) * Ndim + col] = p1;
        }
    }
}

// ---------------------------------------------------------------------------
// Fused synthesizer attention, tensorized tf32, all operands pre-rounded:
//   k/v/w2/ps are tf32-rounded at their producers -> mma loops use pure bit
//   reinterprets (no cvt in hot loops).
// ---------------------------------------------------------------------------
#define PS  2052   // ps row stride: conflict-free fragment reads
#define KSP 68     // ks row stride

__global__ __launch_bounds__(256) void attn_kernel(
    const float* __restrict__ gk, const float* __restrict__ gv,
    const float* __restrict__ w2r, const float* __restrict__ b2,
    float* __restrict__ gy)
{
    extern __shared__ float sm[];
    float* ps   = sm;                    // [16][PS]
    float* ks   = sm + 16 * PS;          // [16][KSP]
    float* sinv = ks + 16 * KSP;         // [16]

    const int t0  = blockIdx.x * 16;
    const int h   = blockIdx.y;
    const int b   = blockIdx.z;
    const int tid = threadIdx.x;
    const int lane = tid & 31;
    const int wid  = tid >> 5;
    const int g    = lane >> 2;
    const int tg   = lane & 3;
    const int Lc   = t0 + 16;

    // ---- load K rows (16x64, already tf32-rounded) ----
#pragma unroll
    for (int i = 0; i < 4; i++) {
        int flat = tid + i * 256;
        int d = flat & 63, r = flat >> 6;
        ks[r * KSP + d] = gk[(size_t)(b * Tq + t0 + r) * Cq + h * HDq + d];
    }
    __syncthreads();

    // ---- preload A fragments (bit reinterpret; values already tf32) ----
    unsigned A0[8], A1[8], A2[8], A3[8];
#pragma unroll
    for (int kf = 0; kf < 8; kf++) {
        A0[kf] = __float_as_uint(ks[g * KSP + kf * 8 + tg]);
        A1[kf] = __float_as_uint(ks[(g + 8) * KSP + kf * 8 + tg]);
        A2[kf] = __float_as_uint(ks[g * KSP + kf * 8 + tg + 4]);
        A3[kf] = __float_as_uint(ks[(g + 8) * KSP + kf * 8 + tg + 4]);
    }

    // ---- score phase: warp w owns column stripes w*8 + 64*j; 2-chain ILP ----
    const float* w2h = w2r + h * HDq * Mq;
    for (int n0 = wid * 8; n0 < Lc; n0 += 128) {
        const int n1 = n0 + 64;
        const bool go1 = (n1 < Lc);
        float d0[4] = {0.f, 0.f, 0.f, 0.f};
        float d1[4] = {0.f, 0.f, 0.f, 0.f};
#pragma unroll
        for (int kf = 0; kf < 8; kf++) {
            const int r0 = (kf * 8 + tg) * Mq;
            const int r4 = (kf * 8 + tg + 4) * Mq;
            unsigned b00 = __float_as_uint(__ldg(&w2h[r0 + n0 + g]));
            unsigned b01 = __float_as_uint(__ldg(&w2h[r4 + n0 + g]));
            mma_tf32(d0[0], d0[1], d0[2], d0[3],
                     A0[kf], A1[kf], A2[kf], A3[kf], b00, b01);
            if (go1) {
                unsigned b10 = __float_as_uint(__ldg(&w2h[r0 + n1 + g]));
                unsigned b11 = __float_as_uint(__ldg(&w2h[r4 + n1 + g]));
                mma_tf32(d1[0], d1[1], d1[2], d1[3],
                         A0[kf], A1[kf], A2[kf], A3[kf], b10, b11);
            }
        }
        {
            float2 bz = *(const float2*)&b2[n0 + 2 * tg];
            float2 p0; p0.x = d0[0] + bz.x; p0.y = d0[1] + bz.y;
            float2 p1; p1.x = d0[2] + bz.x; p1.y = d0[3] + bz.y;
            *(float2*)&ps[g * PS + n0 + 2 * tg] = p0;
            *(float2*)&ps[(g + 8) * PS + n0 + 2 * tg] = p1;
        }
        if (go1) {
            float2 bz = *(const float2*)&b2[n1 + 2 * tg];
            float2 p0; p0.x = d1[0] + bz.x; p0.y = d1[1] + bz.y;
            float2 p1; p1.x = d1[2] + bz.x; p1.y = d1[3] + bz.y;
            *(float2*)&ps[g * PS + n1 + 2 * tg] = p0;
            *(float2*)&ps[(g + 8) * PS + n1 + 2 * tg] = p1;
        }
    }
    __syncthreads();

    // ---- softmax (no max-pass; |logit| << 1). Store tf32-rounded probs. ----
    for (int r = wid; r < 16; r += 8) {
        const int n = t0 + r + 1;
        float* row = ps + r * PS;
        float sum = 0.f;
        for (int m = lane; m < n; m += 32) {
            float e = __expf(row[m]);
            sum += e;
            row[m] = __uint_as_float(f2tf32(e));
        }
#pragma unroll
        for (int off = 16; off; off >>= 1)
            sum += __shfl_xor_sync(0xffffffffu, sum, off);
        if (lane == 0) sinv[r] = 1.f / sum;
        for (int m = n + lane; m < Lc; m += 32) row[m] = 0.f;
    }
    __syncthreads();

    // ---- PV: warp w owns out cols [8w, 8w+8); 2 accumulator chains ----
    {
        const int c0 = wid * 8;
        const float* vb = gv + (size_t)(b * Tq) * Cq + h * HDq + c0 + g;
        float e0[4] = {0.f, 0.f, 0.f, 0.f};
        float e1[4] = {0.f, 0.f, 0.f, 0.f};
        const int nk = Lc >> 3;
        for (int kf = 0; kf < nk; kf += 2) {
            const int l0 = kf * 8;
            const int l1 = l0 + 8;
            unsigned a0 = __float_as_uint(ps[g * PS + l0 + tg]);
            unsigned a1 = __float_as_uint(ps[(g + 8) * PS + l0 + tg]);
            unsigned a2 = __float_as_uint(ps[g * PS + l0 + tg + 4]);
            unsigned a3 = __float_as_uint(ps[(g + 8) * PS + l0 + tg + 4]);
            unsigned b0 = __float_as_uint(__ldg(&vb[(l0 + tg) * Cq]));
            unsigned b1 = __float_as_uint(__ldg(&vb[(l0 + tg + 4) * Cq]));
            mma_tf32(e0[0], e0[1], e0[2], e0[3], a0, a1, a2, a3, b0, b1);
            unsigned c0r = __float_as_uint(ps[g * PS + l1 + tg]);
            unsigned c1r = __float_as_uint(ps[(g + 8) * PS + l1 + tg]);
            unsigned c2r = __float_as_uint(ps[g * PS + l1 + tg + 4]);
            unsigned c3r = __float_as_uint(ps[(g + 8) * PS + l1 + tg + 4]);
            unsigned d0r = __float_as_uint(__ldg(&vb[(l1 + tg) * Cq]));
            unsigned d1r = __float_as_uint(__ldg(&vb[(l1 + tg + 4) * Cq]));
            mma_tf32(e1[0], e1[1], e1[2], e1[3], c0r, c1r, c2r, c3r, d0r, d1r);
        }
        const float ivg = sinv[g];
        const float ivh = sinv[g + 8];
        float2 o0, o1;
        o0.x = (e0[0] + e1[0]) * ivg;
        o0.y = (e0[1] + e1[1]) * ivg;
        o1.x = (e0[2] + e1[2]) * ivh;
        o1.y = (e0[3] + e1[3]) * ivh;
        float* gy0 = gy + (size_t)(b * Tq + t0 + g) * Cq + h * HDq + c0 + 2 * tg;
        float* gy1 = gy + (size_t)(b * Tq + t0 + g + 8) * Cq + h * HDq + c0 + 2 * tg;
        *(float2*)gy0 = o0;
        *(float2*)gy1 = o1;
    }
}

// ---------------------------------------------------------------------------
extern "C" void kernel_launch(void* const* d_in, const int* in_sizes, int n_in,
                              void* d_out, int out_size)
{
    const float* x       = (const float*)d_in[0];
    const float* w1_w    = (const float*)d_in[1];
    const float* w1_b    = (const float*)d_in[2];
    const float* w2      = (const float*)d_in[3];
    const float* b2      = (const float*)d_in[4];
    const float* value_w = (const float*)d_in[5];
    const float* value_b = (const float*)d_in[6];
    const float* proj_w  = (const float*)d_in[7];
    const float* proj_b  = (const float*)d_in[8];
    float* out = (float*)d_out;

    float *pk, *pv, *py, *pw2r;
    unsigned *pahi, *palo, *pwhi, *pwlo;
    cudaGetSymbolAddress((void**)&pk,   g_k);
    cudaGetSymbolAddress((void**)&pv,   g_v);
    cudaGetSymbolAddress((void**)&py,   g_y);
    cudaGetSymbolAddress((void**)&pw2r, g_w2r);
    cudaGetSymbolAddress((void**)&pahi, g_ahi);
    cudaGetSymbolAddress((void**)&palo, g_alo);
    cudaGetSymbolAddress((void**)&pwhi, g_whi);
    cudaGetSymbolAddress((void**)&pwlo, g_wlo);

    const int SMEM_GEMM = 8 * PLW * (int)sizeof(unsigned);          // 80 KB
    const int SMEM_ATTN = (16 * PS + 16 * KSP + 16) * (int)sizeof(float);
    cudaFuncSetAttribute(gemm_ds_kernel<true, true>,
                         cudaFuncAttributeMaxDynamicSharedMemorySize, SMEM_GEMM);
    cudaFuncSetAttribute(gemm_ds_kernel<false, true>,
                         cudaFuncAttributeMaxDynamicSharedMemorySize, SMEM_GEMM);
    cudaFuncSetAttribute(gemm_ds_kernel<false, false>,
                         cudaFuncAttributeMaxDynamicSharedMemorySize, SMEM_GEMM);
    cudaFuncSetAttribute(attn_kernel,
                         cudaFuncAttributeMaxDynamicSharedMemorySize, SMEM_ATTN);

    const int Mrows = Bq * Tq;                 // 4096
    const int NACT4 = Mrows * Cq / 4;          // 1M float4
    const int NW4   = Cq * Cq / 4;             // 256K float4
    const int NW24  = Hq * HDq * Mq / 4;       // 512K float4
    dim3 gemm_grid(Cq / 128, Mrows / 128);     // (8, 32) = 256 CTAs

    // prep: split x, round w2
    split_kernel<<<(NACT4 + 255) / 256, 256>>>(
        (const float4*)x, (uint4*)pahi, (uint4*)palo, NACT4);
    round_kernel<<<(NW24 + 255) / 256, 256>>>(
        (const float4*)w2, (float4*)pw2r, NW24);

    // k = relu(x @ w1^T + b1), tf32-rounded output
    split_kernel<<<(NW4 + 255) / 256, 256>>>(
        (const float4*)w1_w, (uint4*)pwhi, (uint4*)pwlo, NW4);
    gemm_ds_kernel<true, true><<<gemm_grid, 256, SMEM_GEMM>>>(
        pahi, palo, pwhi, pwlo, w1_b, pk, Mrows, Cq, Cq);

    // v = x @ value^T + vb, tf32-rounded output
    split_kernel<<<(NW4 + 255) / 256, 256>>>(
        (const float4*)value_w, (uint4*)pwhi, (uint4*)pwlo, NW4);
    gemm_ds_kernel<false, true><<<gemm_grid, 256, SMEM_GEMM>>>(
        pahi, palo, pwhi, pwlo, value_b, pv, Mrows, Cq, Cq);

    // attention
    dim3 agrid(Tq / 16, Hq, Bq);
    attn_kernel<<<agrid, 256, SMEM_ATTN>>>(pk, pv, pw2r, b2, py);

    // out = y @ proj^T + pb (full fp32 output)
    split_kernel<<<(NACT4 + 255) / 256, 256>>>(
        (const float4*)py, (uint4*)pahi, (uint4*)palo, NACT4);
    split_kernel<<<(NW4 + 255) / 256, 256>>>(
        (const float4*)proj_w, (uint4*)pwhi, (uint4*)pwlo, NW4);
    gemm_ds_kernel<false, false><<<gemm_grid, 256, SMEM_GEMM>>>(
        pahi, palo, pwhi, pwlo, proj_b, out, Mrows, Cq, Cq);
}

// round 7
// speedup vs baseline: 5.0468x; 1.3771x over previous
#include <cuda_runtime.h>
#include <cuda_bf16.h>
#include <math.h>

// Problem constants
#define Bq   2
#define Tq   2048
#define Cq   1024
#define Hq   16
#define HDq  64
#define Mq   2048

// Scratch (allocation-free rule: __device__ globals)
__device__ float    g_k[Bq * Tq * Cq];     // relu(x @ w1^T + b1), tf32-rounded
__device__ float    g_v[Bq * Tq * Cq];     // x @ value^T + vb, tf32-rounded
__device__ float    g_y[Bq * Tq * Cq];     // attention output (pre-proj, fp32)
__device__ unsigned g_ahi[Bq * Tq * Cq];   // activation hi plane (x, then y)
__device__ unsigned g_alo[Bq * Tq * Cq];   // activation lo plane
__device__ unsigned g_whi[Cq * Cq];        // weight hi plane (per-GEMM reuse)
__device__ unsigned g_wlo[Cq * Cq];        // weight lo plane
__device__ float    g_w2r[Hq * HDq * Mq];  // w2 tf32-rounded

// ---------------------------------------------------------------------------
// tf32 / async helpers
// ---------------------------------------------------------------------------
__device__ __forceinline__ unsigned f2tf32(float x) {
    unsigned u;
    asm("cvt.rna.tf32.f32 %0, %1;" : "=r"(u) : "f"(x));
    return u;
}

__device__ __forceinline__ void mma_tf32(
    float& d0, float& d1, float& d2, float& d3,
    unsigned a0, unsigned a1, unsigned a2, unsigned a3,
    unsigned b0, unsigned b1)
{
    asm volatile(
        "mma.sync.aligned.m16n8k8.row.col.f32.tf32.tf32.f32 "
        "{%0,%1,%2,%3}, {%4,%5,%6,%7}, {%8,%9}, {%0,%1,%2,%3};"
        : "+f"(d0), "+f"(d1), "+f"(d2), "+f"(d3)
        : "r"(a0), "r"(a1), "r"(a2), "r"(a3), "r"(b0), "r"(b1));
}

__device__ __forceinline__ void cp_async16(void* s, const void* g) {
    unsigned sa = (unsigned)__cvta_generic_to_shared(s);
    asm volatile("cp.async.cg.shared.global [%0], [%1], 16;" :: "r"(sa), "l"(g));
}

// ---------------------------------------------------------------------------
// Prep kernels
// ---------------------------------------------------------------------------
__global__ __launch_bounds__(256) void split_kernel(
    const float4* __restrict__ in, uint4* __restrict__ hi,
    uint4* __restrict__ lo, int n4)
{
    int i = blockIdx.x * 256 + threadIdx.x;
    if (i < n4) {
        float4 v = in[i];
        uint4 h, l;
        h.x = f2tf32(v.x); l.x = f2tf32(v.x - __uint_as_float(h.x));
        h.y = f2tf32(v.y); l.y = f2tf32(v.y - __uint_as_float(h.y));
        h.z = f2tf32(v.z); l.z = f2tf32(v.z - __uint_as_float(h.z));
        h.w = f2tf32(v.w); l.w = f2tf32(v.w - __uint_as_float(h.w));
        hi[i] = h; lo[i] = l;
    }
}

__global__ __launch_bounds__(256) void round_kernel(
    const float4* __restrict__ in, float4* __restrict__ out, int n4)
{
    int i = blockIdx.x * 256 + threadIdx.x;
    if (i < n4) {
        float4 v = in[i];
        float4 o;
        o.x = __uint_as_float(f2tf32(v.x));
        o.y = __uint_as_float(f2tf32(v.y));
        o.z = __uint_as_float(f2tf32(v.z));
        o.w = __uint_as_float(f2tf32(v.w));
        out[i] = o;
    }
}

// ---------------------------------------------------------------------------
// Dense GEMM (unchanged from R6): pre-split operands, cp.async 2-stage, 3xTF32
// ---------------------------------------------------------------------------
#define ST   20
#define PLW  2560

template <bool RELU, bool ROUND_OUT>
__global__ __launch_bounds__(256) void gemm_ds_kernel(
    const unsigned* __restrict__ Ahi, const unsigned* __restrict__ Alo,
    const unsigned* __restrict__ Whi, const unsigned* __restrict__ Wlo,
    const float* __restrict__ bias, float* __restrict__ Cmat,
    int Mdim, int Ndim, int Kdim)
{
    extern __shared__ unsigned smu[];
    unsigned* sAh = smu;
    unsigned* sAl = sAh + 2 * PLW;
    unsigned* sBh = sAl + 2 * PLW;
    unsigned* sBl = sBh + 2 * PLW;

    const int tid  = threadIdx.x;
    const int lane = tid & 31;
    const int wid  = tid >> 5;
    const int wm   = (wid & 3) * 32;
    const int wn   = (wid >> 2) * 64;
    const int g    = lane >> 2;
    const int tg   = lane & 3;

    const int m0 = blockIdx.y * 128;
    const int n0 = blockIdx.x * 128;
    const int NK = Kdim >> 4;

    float acc[2][8][4];
#pragma unroll
    for (int im = 0; im < 2; im++)
#pragma unroll
        for (int in = 0; in < 8; in++)
#pragma unroll
            for (int e = 0; e < 4; e++) acc[im][in][e] = 0.f;

    auto load_stage = [&](int kt, int st) {
        const int k0 = kt << 4;
#pragma unroll
        for (int i = 0; i < 8; i++) {
            int cc = tid + (i & 1) * 256;
            int r  = cc >> 2;
            int k4 = (cc & 3) << 2;
            if ((i >> 1) == 0)
                cp_async16(&sAh[st * PLW + r * ST + k4],
                           &Ahi[(size_t)(m0 + r) * Kdim + k0 + k4]);
            else if ((i >> 1) == 1)
                cp_async16(&sAl[st * PLW + r * ST + k4],
                           &Alo[(size_t)(m0 + r) * Kdim + k0 + k4]);
            else if ((i >> 1) == 2)
                cp_async16(&sBh[st * PLW + r * ST + k4],
                           &Whi[(size_t)(n0 + r) * Kdim + k0 + k4]);
            else
                cp_async16(&sBl[st * PLW + r * ST + k4],
                           &Wlo[(size_t)(n0 + r) * Kdim + k0 + k4]);
        }
        asm volatile("cp.async.commit_group;" ::: "memory");
    };

    load_stage(0, 0);

    for (int kt = 0; kt < NK; kt++) {
        const int cur = kt & 1;
        if (kt + 1 < NK) {
            load_stage(kt + 1, (kt + 1) & 1);
            asm volatile("cp.async.wait_group 1;" ::: "memory");
        } else {
            asm volatile("cp.async.wait_group 0;" ::: "memory");
        }
        __syncthreads();

        const unsigned* pAh = sAh + cur * PLW;
        const unsigned* pAl = sAl + cur * PLW;
        const unsigned* pBh = sBh + cur * PLW;
        const unsigned* pBl = sBl + cur * PLW;

#pragma unroll
        for (int ks = 0; ks < 16; ks += 8) {
            unsigned ah[2][4], al[2][4], bh[8][2], bl[8][2];
#pragma unroll
            for (int im = 0; im < 2; im++) {
                int r = wm + im * 16 + g;
                ah[im][0] = pAh[r * ST + ks + tg];
                ah[im][1] = pAh[(r + 8) * ST + ks + tg];
                ah[im][2] = pAh[r * ST + ks + tg + 4];
                ah[im][3] = pAh[(r + 8) * ST + ks + tg + 4];
                al[im][0] = pAl[r * ST + ks + tg];
                al[im][1] = pAl[(r + 8) * ST + ks + tg];
                al[im][2] = pAl[r * ST + ks + tg + 4];
                al[im][3] = pAl[(r + 8) * ST + ks + tg + 4];
            }
#pragma unroll
            for (int in = 0; in < 8; in++) {
                int c = wn + in * 8 + g;
                bh[in][0] = pBh[c * ST + ks + tg];
                bh[in][1] = pBh[c * ST + ks + tg + 4];
                bl[in][0] = pBl[c * ST + ks + tg];
                bl[in][1] = pBl[c * ST + ks + tg + 4];
            }
#pragma unroll
            for (int im = 0; im < 2; im++)
#pragma unroll
                for (int in = 0; in < 8; in++) {
                    float* d = acc[im][in];
                    mma_tf32(d[0], d[1], d[2], d[3],
                             ah[im][0], ah[im][1], ah[im][2], ah[im][3],
                             bh[in][0], bh[in][1]);
                    mma_tf32(d[0], d[1], d[2], d[3],
                             ah[im][0], ah[im][1], ah[im][2], ah[im][3],
                             bl[in][0], bl[in][1]);
                    mma_tf32(d[0], d[1], d[2], d[3],
                             al[im][0], al[im][1], al[im][2], al[im][3],
                             bh[in][0], bh[in][1]);
                }
        }
        __syncthreads();
    }

#pragma unroll
    for (int in = 0; in < 8; in++) {
        int col = n0 + wn + in * 8 + 2 * tg;
        float2 bz = *(const float2*)&bias[col];
#pragma unroll
        for (int im = 0; im < 2; im++) {
            int row = m0 + wm + im * 16 + g;
            float v0 = acc[im][in][0] + bz.x;
            float v1 = acc[im][in][1] + bz.y;
            float v2 = acc[im][in][2] + bz.x;
            float v3 = acc[im][in][3] + bz.y;
            if (RELU) {
                v0 = fmaxf(v0, 0.f); v1 = fmaxf(v1, 0.f);
                v2 = fmaxf(v2, 0.f); v3 = fmaxf(v3, 0.f);
            }
            if (ROUND_OUT) {
                v0 = __uint_as_float(f2tf32(v0));
                v1 = __uint_as_float(f2tf32(v1));
                v2 = __uint_as_float(f2tf32(v2));
                v3 = __uint_as_float(f2tf32(v3));
            }
            float2 p0; p0.x = v0; p0.y = v1;
            float2 p1; p1.x = v2; p1.y = v3;
            *(float2*)&Cmat[(size_t)row * Ndim + col] = p0;
            *(float2*)&Cmat[(size_t)(row + 8) * Ndim + col] = p1;
        }
    }
}

// ---------------------------------------------------------------------------
// Chunked fused attention v2: block = (b, h, 64 query rows), 256 threads.
// Stream 128-col chunks: cp.async-stage w2[64x128] + V[128x64] (dbl-buffered),
// score mma -> exp+mask -> ps smem -> PV mma accumulate. No max-pass, no
// rescale: num/denom are linear accumulations. All operands pre-tf32.
// smem strides chosen conflict-free: ks 68, w2s 136, vs 72, ps 132.
// ---------------------------------------------------------------------------
#define BMq  64
#define BCq  128
#define KSP2 68
#define W2S  136
#define VSS  72
#define PSS  132

__global__ __launch_bounds__(256) void attn2_kernel(
    const float* __restrict__ gk, const float* __restrict__ gv,
    const float* __restrict__ w2r, const float* __restrict__ b2,
    float* __restrict__ gy)
{
    extern __shared__ float sm[];
    float* ks    = sm;                         // [64][68]
    float* w2s   = ks + 64 * KSP2;             // [2][64][136]
    float* vs    = w2s + 2 * 64 * W2S;         // [2][128][72]
    float* ps    = vs + 2 * 128 * VSS;         // [64][132]
    float* dpart = ps + 64 * PSS;              // [8][64]
    float* denom = dpart + 8 * 64;             // [64]

    const int t0  = blockIdx.x * BMq;
    const int h   = blockIdx.y;
    const int b   = blockIdx.z;
    const int tid = threadIdx.x;
    const int lane = tid & 31;
    const int wid  = tid >> 5;
    const int g    = lane >> 2;
    const int tg   = lane & 3;

    const int ncols = t0 + BMq;
    const int nch   = (ncols + BCq - 1) >> 7;   // c0max=1920 -> never OOB

    auto stage = [&](int c, int buf) {
        const int c0 = c << 7;
        float* w2d = w2s + buf * 64 * W2S;
        float* vsd = vs + buf * 128 * VSS;
        const float* w2g = w2r + (size_t)h * HDq * Mq + c0;
        const float* vg  = gv + (size_t)b * Tq * Cq + (size_t)c0 * Cq + h * HDq;
#pragma unroll
        for (int i = 0; i < 8; i++) {           // w2: 64x128 = 2048 16B chunks
            int cc = tid + i * 256;
            int d  = cc >> 5;
            int m4 = (cc & 31) << 2;
            cp_async16(&w2d[d * W2S + m4], &w2g[(size_t)d * Mq + m4]);
        }
#pragma unroll
        for (int i = 0; i < 8; i++) {           // V: 128x64 = 2048 16B chunks
            int cc = tid + i * 256;
            int l  = cc >> 4;
            int d4 = (cc & 15) << 2;
            cp_async16(&vsd[l * VSS + d4], &vg[(size_t)l * Cq + d4]);
        }
        asm volatile("cp.async.commit_group;" ::: "memory");
    };

    // stage K (once) + chunk 0 in group 0
    {
#pragma unroll
        for (int i = 0; i < 4; i++) {           // K: 64x64 = 1024 16B chunks
            int cc = tid + i * 256;
            int r  = cc >> 4;
            int d4 = (cc & 15) << 2;
            cp_async16(&ks[r * KSP2 + d4],
                       &gk[(size_t)(b * Tq + t0 + r) * Cq + h * HDq + d4]);
        }
        stage(0, 0);
    }

    float o[4][4];      // PV accumulators: warp cols [wid*8, wid*8+8)
    float dp[4][2];     // denom partials (im, row-half)
#pragma unroll
    for (int im = 0; im < 4; im++) {
#pragma unroll
        for (int e = 0; e < 4; e++) o[im][e] = 0.f;
        dp[im][0] = 0.f; dp[im][1] = 0.f;
    }

    for (int c = 0; c < nch; c++) {
        const int buf = c & 1;
        if (c + 1 < nch) {
            stage(c + 1, (c + 1) & 1);
            asm volatile("cp.async.wait_group 1;" ::: "memory");
        } else {
            asm volatile("cp.async.wait_group 0;" ::: "memory");
        }
        __syncthreads();

        // ---- score mma: warp owns chunk cols [wid*16, wid*16+16) ----
        const float* w2c = w2s + buf * 64 * W2S;
        float d[4][2][4];
#pragma unroll
        for (int im = 0; im < 4; im++)
#pragma unroll
            for (int in = 0; in < 2; in++)
#pragma unroll
                for (int e = 0; e < 4; e++) d[im][in][e] = 0.f;

#pragma unroll
        for (int kf = 0; kf < 8; kf++) {
            unsigned a0[4], a1[4], a2[4], a3[4];
#pragma unroll
            for (int im = 0; im < 4; im++) {
                int r = im * 16 + g;
                a0[im] = __float_as_uint(ks[r * KSP2 + kf * 8 + tg]);
                a1[im] = __float_as_uint(ks[(r + 8) * KSP2 + kf * 8 + tg]);
                a2[im] = __float_as_uint(ks[r * KSP2 + kf * 8 + tg + 4]);
                a3[im] = __float_as_uint(ks[(r + 8) * KSP2 + kf * 8 + tg + 4]);
            }
#pragma unroll
            for (int in = 0; in < 2; in++) {
                int cc = wid * 16 + in * 8 + g;
                unsigned b0 = __float_as_uint(w2c[(kf * 8 + tg) * W2S + cc]);
                unsigned b1 = __float_as_uint(w2c[(kf * 8 + tg + 4) * W2S + cc]);
#pragma unroll
                for (int im = 0; im < 4; im++)
                    mma_tf32(d[im][in][0], d[im][in][1], d[im][in][2], d[im][in][3],
                             a0[im], a1[im], a2[im], a3[im], b0, b1);
            }
        }

        // ---- bias + exp + causal mask + ps store + denom partials ----
        const int cbase = (c << 7) + wid * 16;
#pragma unroll
        for (int in = 0; in < 2; in++) {
            const int colb = cbase + in * 8 + 2 * tg;
            float2 bz = *(const float2*)&b2[colb];
#pragma unroll
            for (int im = 0; im < 4; im++) {
                const int r1 = t0 + im * 16 + g;
                const int r2 = r1 + 8;
                float s0 = d[im][in][0] + bz.x;
                float s1 = d[im][in][1] + bz.y;
                float s2 = d[im][in][2] + bz.x;
                float s3 = d[im][in][3] + bz.y;
                float e0 = (colb     <= r1) ? __expf(s0) : 0.f;
                float e1 = (colb + 1 <= r1) ? __expf(s1) : 0.f;
                float e2 = (colb     <= r2) ? __expf(s2) : 0.f;
                float e3 = (colb + 1 <= r2) ? __expf(s3) : 0.f;
                dp[im][0] += e0 + e1;
                dp[im][1] += e2 + e3;
                float2 p0, p1;
                p0.x = __uint_as_float(f2tf32(e0));
                p0.y = __uint_as_float(f2tf32(e1));
                p1.x = __uint_as_float(f2tf32(e2));
                p1.y = __uint_as_float(f2tf32(e3));
                int loc = wid * 16 + in * 8 + 2 * tg;
                *(float2*)&ps[(im * 16 + g) * PSS + loc] = p0;
                *(float2*)&ps[(im * 16 + 8 + g) * PSS + loc] = p1;
            }
        }
        __syncthreads();

        // ---- PV mma: warp owns out cols [wid*8, wid*8+8) ----
        const float* vc = vs + buf * 128 * VSS;
#pragma unroll 4
        for (int kf = 0; kf < 16; kf++) {
            const int l0 = kf * 8;
            unsigned b0 = __float_as_uint(vc[(l0 + tg) * VSS + wid * 8 + g]);
            unsigned b1 = __float_as_uint(vc[(l0 + tg + 4) * VSS + wid * 8 + g]);
#pragma unroll
            for (int im = 0; im < 4; im++) {
                int r = im * 16 + g;
                unsigned a0 = __float_as_uint(ps[r * PSS + l0 + tg]);
                unsigned a1 = __float_as_uint(ps[(r + 8) * PSS + l0 + tg]);
                unsigned a2 = __float_as_uint(ps[r * PSS + l0 + tg + 4]);
                unsigned a3 = __float_as_uint(ps[(r + 8) * PSS + l0 + tg + 4]);
                mma_tf32(o[im][0], o[im][1], o[im][2], o[im][3],
                         a0, a1, a2, a3, b0, b1);
            }
        }
        __syncthreads();
    }

    // ---- denominator reduction: tg lanes -> warps -> 1/sum ----
#pragma unroll
    for (int im = 0; im < 4; im++) {
#pragma unroll
        for (int hf = 0; hf < 2; hf++) {
            float v = dp[im][hf];
            v += __shfl_xor_sync(0xffffffffu, v, 1);
            v += __shfl_xor_sync(0xffffffffu, v, 2);
            dp[im][hf] = v;
        }
    }
    if (tg == 0) {
#pragma unroll
        for (int im = 0; im < 4; im++) {
            dpart[wid * 64 + im * 16 + g]     = dp[im][0];
            dpart[wid * 64 + im * 16 + 8 + g] = dp[im][1];
        }
    }
    __syncthreads();
    if (tid < 64) {
        float s = 0.f;
#pragma unroll
        for (int w = 0; w < 8; w++) s += dpart[w * 64 + tid];
        denom[tid] = 1.f / s;
    }
    __syncthreads();

    // ---- output: rows im*16+g(+8), cols h*64 + wid*8 + 2tg ----
#pragma unroll
    for (int im = 0; im < 4; im++) {
        const int r = im * 16 + g;
        const float iv1 = denom[r];
        const float iv2 = denom[r + 8];
        float2 o1, o2;
        o1.x = o[im][0] * iv1; o1.y = o[im][1] * iv1;
        o2.x = o[im][2] * iv2; o2.y = o[im][3] * iv2;
        float* p1 = gy + (size_t)(b * Tq + t0 + r) * Cq + h * HDq + wid * 8 + 2 * tg;
        float* p2 = gy + (size_t)(b * Tq + t0 + r + 8) * Cq + h * HDq + wid * 8 + 2 * tg;
        *(float2*)p1 = o1;
        *(float2*)p2 = o2;
    }
}

// ---------------------------------------------------------------------------
extern "C" void kernel_launch(void* const* d_in, const int* in_sizes, int n_in,
                              void* d_out, int out_size)
{
    const float* x       = (const float*)d_in[0];
    const float* w1_w    = (const float*)d_in[1];
    const float* w1_b    = (const float*)d_in[2];
    const float* w2      = (const float*)d_in[3];
    const float* b2      = (const float*)d_in[4];
    const float* value_w = (const float*)d_in[5];
    const float* value_b = (const float*)d_in[6];
    const float* proj_w  = (const float*)d_in[7];
    const float* proj_b  = (const float*)d_in[8];
    float* out = (float*)d_out;

    float *pk, *pv, *py, *pw2r;
    unsigned *pahi, *palo, *pwhi, *pwlo;
    cudaGetSymbolAddress((void**)&pk,   g_k);
    cudaGetSymbolAddress((void**)&pv,   g_v);
    cudaGetSymbolAddress((void**)&py,   g_y);
    cudaGetSymbolAddress((void**)&pw2r, g_w2r);
    cudaGetSymbolAddress((void**)&pahi, g_ahi);
    cudaGetSymbolAddress((void**)&palo, g_alo);
    cudaGetSymbolAddress((void**)&pwhi, g_whi);
    cudaGetSymbolAddress((void**)&pwlo, g_wlo);

    const int SMEM_GEMM = 8 * PLW * (int)sizeof(unsigned);            // 80 KB
    const int SMEM_ATTN = (64 * KSP2 + 2 * 64 * W2S + 2 * 128 * VSS +
                           64 * PSS + 8 * 64 + 64) * (int)sizeof(float); // ~192 KB
    cudaFuncSetAttribute(gemm_ds_kernel<true, true>,
                         cudaFuncAttributeMaxDynamicSharedMemorySize, SMEM_GEMM);
    cudaFuncSetAttribute(gemm_ds_kernel<false, true>,
                         cudaFuncAttributeMaxDynamicSharedMemorySize, SMEM_GEMM);
    cudaFuncSetAttribute(gemm_ds_kernel<false, false>,
                         cudaFuncAttributeMaxDynamicSharedMemorySize, SMEM_GEMM);
    cudaFuncSetAttribute(attn2_kernel,
                         cudaFuncAttributeMaxDynamicSharedMemorySize, SMEM_ATTN);

    const int Mrows = Bq * Tq;                 // 4096
    const int NACT4 = Mrows * Cq / 4;
    const int NW4   = Cq * Cq / 4;
    const int NW24  = Hq * HDq * Mq / 4;
    dim3 gemm_grid(Cq / 128, Mrows / 128);     // (8, 32)

    split_kernel<<<(NACT4 + 255) / 256, 256>>>(
        (const float4*)x, (uint4*)pahi, (uint4*)palo, NACT4);
    round_kernel<<<(NW24 + 255) / 256, 256>>>(
        (const float4*)w2, (float4*)pw2r, NW24);

    split_kernel<<<(NW4 + 255) / 256, 256>>>(
        (const float4*)w1_w, (uint4*)pwhi, (uint4*)pwlo, NW4);
    gemm_ds_kernel<true, true><<<gemm_grid, 256, SMEM_GEMM>>>(
        pahi, palo, pwhi, pwlo, w1_b, pk, Mrows, Cq, Cq);

    split_kernel<<<(NW4 + 255) / 256, 256>>>(
        (const float4*)value_w, (uint4*)pwhi, (uint4*)pwlo, NW4);
    gemm_ds_kernel<false, true><<<gemm_grid, 256, SMEM_GEMM>>>(
        pahi, palo, pwhi, pwlo, value_b, pv, Mrows, Cq, Cq);

    dim3 agrid(Tq / BMq, Hq, Bq);              // (32, 16, 2)
    attn2_kernel<<<agrid, 256, SMEM_ATTN>>>(pk, pv, pw2r, b2, py);

    split_kernel<<<(NACT4 + 255) / 256, 256>>>(
        (const float4*)py, (uint4*)pahi, (uint4*)palo, NACT4);
    split_kernel<<<(NW4 + 255) / 256, 256>>>(
        (const float4*)proj_w, (uint4*)pwhi, (uint4*)pwlo, NW4);
    gemm_ds_kernel<false, false><<<gemm_grid, 256, SMEM_GEMM>>>(
        pahi, palo, pwhi, pwlo, proj_b, out, Mrows, Cq, Cq);
}

// round 8
// speedup vs baseline: 7.5897x; 1.5039x over previous
#include <cuda_runtime.h>
#include <cuda_bf16.h>
#include <math.h>

// Problem constants
#define Bq   2
#define Tq   2048
#define Cq   1024
#define Hq   16
#define HDq  64
#define Mq   2048

// Scratch (allocation-free rule: __device__ globals)
__device__ float         g_k[Bq * Tq * Cq];    // relu(x@w1^T+b1), tf32-rounded
__device__ float         g_v[Bq * Tq * Cq];    // x@value^T+vb, tf32-rounded
__device__ __nv_bfloat16 g_ahi[Bq * Tq * Cq];  // activation hi plane (x, then y)
__device__ __nv_bfloat16 g_alo[Bq * Tq * Cq];  // activation lo plane
__device__ __nv_bfloat16 g_whi[Cq * Cq];       // weight hi plane (per-GEMM reuse)
__device__ __nv_bfloat16 g_wlo[Cq * Cq];       // weight lo plane
__device__ float         g_w2r[Hq * HDq * Mq]; // w2 tf32-rounded

// ---------------------------------------------------------------------------
// helpers
// ---------------------------------------------------------------------------
__device__ __forceinline__ unsigned f2tf32(float x) {
    unsigned u;
    asm("cvt.rna.tf32.f32 %0, %1;" : "=r"(u) : "f"(x));
    return u;
}

__device__ __forceinline__ void mma_tf32(
    float& d0, float& d1, float& d2, float& d3,
    unsigned a0, unsigned a1, unsigned a2, unsigned a3,
    unsigned b0, unsigned b1)
{
    asm volatile(
        "mma.sync.aligned.m16n8k8.row.col.f32.tf32.tf32.f32 "
        "{%0,%1,%2,%3}, {%4,%5,%6,%7}, {%8,%9}, {%0,%1,%2,%3};"
        : "+f"(d0), "+f"(d1), "+f"(d2), "+f"(d3)
        : "r"(a0), "r"(a1), "r"(a2), "r"(a3), "r"(b0), "r"(b1));
}

__device__ __forceinline__ void mma_bf16(
    float& d0, float& d1, float& d2, float& d3,
    unsigned a0, unsigned a1, unsigned a2, unsigned a3,
    unsigned b0, unsigned b1)
{
    asm volatile(
        "mma.sync.aligned.m16n8k16.row.col.f32.bf16.bf16.f32 "
        "{%0,%1,%2,%3}, {%4,%5,%6,%7}, {%8,%9}, {%0,%1,%2,%3};"
        : "+f"(d0), "+f"(d1), "+f"(d2), "+f"(d3)
        : "r"(a0), "r"(a1), "r"(a2), "r"(a3), "r"(b0), "r"(b1));
}

__device__ __forceinline__ void cp_async16(void* s, const void* g) {
    unsigned sa = (unsigned)__cvta_generic_to_shared(s);
    asm volatile("cp.async.cg.shared.global [%0], [%1], 16;" :: "r"(sa), "l"(g));
}

__device__ __forceinline__ void bf16_split(float v, __nv_bfloat16& h, __nv_bfloat16& l) {
    h = __float2bfloat16_rn(v);
    l = __float2bfloat16_rn(v - __bfloat162float(h));
}

// ---------------------------------------------------------------------------
// Prep kernels
// ---------------------------------------------------------------------------
__global__ __launch_bounds__(256) void split_bf16_kernel(
    const float4* __restrict__ in, __nv_bfloat162* __restrict__ hi,
    __nv_bfloat162* __restrict__ lo, int n4)
{
    int i = blockIdx.x * 256 + threadIdx.x;
    if (i < n4) {
        float4 v = in[i];
        __nv_bfloat16 hx, lx, hy, ly, hz, lz, hw, lw;
        bf16_split(v.x, hx, lx);
        bf16_split(v.y, hy, ly);
        bf16_split(v.z, hz, lz);
        bf16_split(v.w, hw, lw);
        __nv_bfloat162 h0; h0.x = hx; h0.y = hy;
        __nv_bfloat162 h1; h1.x = hz; h1.y = hw;
        __nv_bfloat162 l0; l0.x = lx; l0.y = ly;
        __nv_bfloat162 l1; l1.x = lz; l1.y = lw;
        hi[2 * i] = h0; hi[2 * i + 1] = h1;
        lo[2 * i] = l0; lo[2 * i + 1] = l1;
    }
}

__global__ __launch_bounds__(256) void round_kernel(
    const float4* __restrict__ in, float4* __restrict__ out, int n4)
{
    int i = blockIdx.x * 256 + threadIdx.x;
    if (i < n4) {
        float4 v = in[i];
        float4 o;
        o.x = __uint_as_float(f2tf32(v.x));
        o.y = __uint_as_float(f2tf32(v.y));
        o.z = __uint_as_float(f2tf32(v.z));
        o.w = __uint_as_float(f2tf32(v.w));
        out[i] = o;
    }
}

// ---------------------------------------------------------------------------
// Dense GEMM via 3x bf16 hi/lo mma (hh+hl+lh), cp.async 2-stage pipeline:
//   C[M,N] = act(A[M,K] @ W[N,K]^T + bias[N])
// Block 128x128, K-tile 32 elts (16 k-pair words), 8 warps (4m x 2n).
// smem word layout identical to R6/R7 (ST=20, proven conflict-free);
// each 32-bit word packs 2 consecutive-k bf16 (matches m16n8k16 fragments).
// ---------------------------------------------------------------------------
#define ST   20
#define PLW  2560   // 128 * ST words per plane-stage

template <bool RELU, bool ROUND_OUT>
__global__ __launch_bounds__(256) void gemm_bf16_kernel(
    const __nv_bfloat16* __restrict__ Ahi, const __nv_bfloat16* __restrict__ Alo,
    const __nv_bfloat16* __restrict__ Whi, const __nv_bfloat16* __restrict__ Wlo,
    const float* __restrict__ bias, float* __restrict__ Cmat,
    int Mdim, int Ndim, int Kdim)
{
    extern __shared__ unsigned smu[];
    unsigned* sAh = smu;
    unsigned* sAl = sAh + 2 * PLW;
    unsigned* sBh = sAl + 2 * PLW;
    unsigned* sBl = sBh + 2 * PLW;

    const int tid  = threadIdx.x;
    const int lane = tid & 31;
    const int wid  = tid >> 5;
    const int wm   = (wid & 3) * 32;
    const int wn   = (wid >> 2) * 64;
    const int g    = lane >> 2;
    const int tg   = lane & 3;

    const int m0 = blockIdx.y * 128;
    const int n0 = blockIdx.x * 128;
    const int NK = Kdim >> 5;          // k32 tiles

    float acc[2][8][4];
#pragma unroll
    for (int im = 0; im < 2; im++)
#pragma unroll
        for (int in = 0; in < 8; in++)
#pragma unroll
            for (int e = 0; e < 4; e++) acc[im][in][e] = 0.f;

    // per stage/plane: 128 rows x 32 elts x 2B = 8KB = 512 16B-chunks
    auto load_stage = [&](int kt, int st) {
        const int k0 = kt << 5;
#pragma unroll
        for (int i = 0; i < 8; i++) {
            int cc = tid + (i & 1) * 256;   // 0..511
            int r  = cc >> 2;               // 0..127
            int j  = cc & 3;                // 16B chunk = 8 elts = 4 words
            if ((i >> 1) == 0)
                cp_async16(&sAh[st * PLW + r * ST + 4 * j],
                           &Ahi[(size_t)(m0 + r) * Kdim + k0 + 8 * j]);
            else if ((i >> 1) == 1)
                cp_async16(&sAl[st * PLW + r * ST + 4 * j],
                           &Alo[(size_t)(m0 + r) * Kdim + k0 + 8 * j]);
            else if ((i >> 1) == 2)
                cp_async16(&sBh[st * PLW + r * ST + 4 * j],
                           &Whi[(size_t)(n0 + r) * Kdim + k0 + 8 * j]);
            else
                cp_async16(&sBl[st * PLW + r * ST + 4 * j],
                           &Wlo[(size_t)(n0 + r) * Kdim + k0 + 8 * j]);
        }
        asm volatile("cp.async.commit_group;" ::: "memory");
    };

    load_stage(0, 0);

    for (int kt = 0; kt < NK; kt++) {
        const int cur = kt & 1;
        if (kt + 1 < NK) {
            load_stage(kt + 1, (kt + 1) & 1);
            asm volatile("cp.async.wait_group 1;" ::: "memory");
        } else {
            asm volatile("cp.async.wait_group 0;" ::: "memory");
        }
        __syncthreads();

        const unsigned* pAh = sAh + cur * PLW;
        const unsigned* pAl = sAl + cur * PLW;
        const unsigned* pBh = sBh + cur * PLW;
        const unsigned* pBl = sBl + cur * PLW;

#pragma unroll
        for (int kw = 0; kw < 16; kw += 8) {   // two k16 steps per tile
            unsigned ah[2][4], al[2][4], bh[8][2], bl[8][2];
#pragma unroll
            for (int im = 0; im < 2; im++) {
                int r = wm + im * 16 + g;
                ah[im][0] = pAh[r * ST + kw + tg];
                ah[im][1] = pAh[(r + 8) * ST + kw + tg];
                ah[im][2] = pAh[r * ST + kw + tg + 4];
                ah[im][3] = pAh[(r + 8) * ST + kw + tg + 4];
                al[im][0] = pAl[r * ST + kw + tg];
                al[im][1] = pAl[(r + 8) * ST + kw + tg];
                al[im][2] = pAl[r * ST + kw + tg + 4];
                al[im][3] = pAl[(r + 8) * ST + kw + tg + 4];
            }
#pragma unroll
            for (int in = 0; in < 8; in++) {
                int c = wn + in * 8 + g;
                bh[in][0] = pBh[c * ST + kw + tg];
                bh[in][1] = pBh[c * ST + kw + tg + 4];
                bl[in][0] = pBl[c * ST + kw + tg];
                bl[in][1] = pBl[c * ST + kw + tg + 4];
            }
#pragma unroll
            for (int im = 0; im < 2; im++)
#pragma unroll
                for (int in = 0; in < 8; in++) {
                    float* d = acc[im][in];
                    mma_bf16(d[0], d[1], d[2], d[3],
                             ah[im][0], ah[im][1], ah[im][2], ah[im][3],
                             bh[in][0], bh[in][1]);
                    mma_bf16(d[0], d[1], d[2], d[3],
                             ah[im][0], ah[im][1], ah[im][2], ah[im][3],
                             bl[in][0], bl[in][1]);
                    mma_bf16(d[0], d[1], d[2], d[3],
                             al[im][0], al[im][1], al[im][2], al[im][3],
                             bh[in][0], bh[in][1]);
                }
        }
        __syncthreads();
    }

#pragma unroll
    for (int in = 0; in < 8; in++) {
        int col = n0 + wn + in * 8 + 2 * tg;
        float2 bz = *(const float2*)&bias[col];
#pragma unroll
        for (int im = 0; im < 2; im++) {
            int row = m0 + wm + im * 16 + g;
            float v0 = acc[im][in][0] + bz.x;
            float v1 = acc[im][in][1] + bz.y;
            float v2 = acc[im][in][2] + bz.x;
            float v3 = acc[im][in][3] + bz.y;
            if (RELU) {
                v0 = fmaxf(v0, 0.f); v1 = fmaxf(v1, 0.f);
                v2 = fmaxf(v2, 0.f); v3 = fmaxf(v3, 0.f);
            }
            if (ROUND_OUT) {
                v0 = __uint_as_float(f2tf32(v0));
                v1 = __uint_as_float(f2tf32(v1));
                v2 = __uint_as_float(f2tf32(v2));
                v3 = __uint_as_float(f2tf32(v3));
            }
            float2 p0; p0.x = v0; p0.y = v1;
            float2 p1; p1.x = v2; p1.y = v3;
            *(float2*)&Cmat[(size_t)row * Ndim + col] = p0;
            *(float2*)&Cmat[(size_t)(row + 8) * Ndim + col] = p1;
        }
    }
}

// ---------------------------------------------------------------------------
// Chunked fused attention (R7 design, tf32 mma): block = (b, h, 64 q rows).
// NEW: epilogue emits y directly as bf16 hi/lo planes for the proj GEMM.
// ---------------------------------------------------------------------------
#define BMq  64
#define BCq  128
#define KSP2 68
#define W2S  136
#define VSS  72
#define PSS  132

__global__ __launch_bounds__(256) void attn2_kernel(
    const float* __restrict__ gk, const float* __restrict__ gv,
    const float* __restrict__ w2r, const float* __restrict__ b2,
    __nv_bfloat16* __restrict__ yhi, __nv_bfloat16* __restrict__ ylo)
{
    extern __shared__ float sm[];
    float* ks    = sm;                         // [64][68]
    float* w2s   = ks + 64 * KSP2;             // [2][64][136]
    float* vs    = w2s + 2 * 64 * W2S;         // [2][128][72]
    float* ps    = vs + 2 * 128 * VSS;         // [64][132]
    float* dpart = ps + 64 * PSS;              // [8][64]
    float* denom = dpart + 8 * 64;             // [64]

    const int t0  = blockIdx.x * BMq;
    const int h   = blockIdx.y;
    const int bb_ = blockIdx.z;
    const int tid = threadIdx.x;
    const int lane = tid & 31;
    const int wid  = tid >> 5;
    const int g    = lane >> 2;
    const int tg   = lane & 3;

    const int ncols = t0 + BMq;
    const int nch   = (ncols + BCq - 1) >> 7;

    auto stage = [&](int c, int buf) {
        const int c0 = c << 7;
        float* w2d = w2s + buf * 64 * W2S;
        float* vsd = vs + buf * 128 * VSS;
        const float* w2g = w2r + (size_t)h * HDq * Mq + c0;
        const float* vg  = gv + (size_t)bb_ * Tq * Cq + (size_t)c0 * Cq + h * HDq;
#pragma unroll
        for (int i = 0; i < 8; i++) {
            int cc = tid + i * 256;
            int d  = cc >> 5;
            int m4 = (cc & 31) << 2;
            cp_async16(&w2d[d * W2S + m4], &w2g[(size_t)d * Mq + m4]);
        }
#pragma unroll
        for (int i = 0; i < 8; i++) {
            int cc = tid + i * 256;
            int l  = cc >> 4;
            int d4 = (cc & 15) << 2;
            cp_async16(&vsd[l * VSS + d4], &vg[(size_t)l * Cq + d4]);
        }
        asm volatile("cp.async.commit_group;" ::: "memory");
    };

    {
#pragma unroll
        for (int i = 0; i < 4; i++) {
            int cc = tid + i * 256;
            int r  = cc >> 4;
            int d4 = (cc & 15) << 2;
            cp_async16(&ks[r * KSP2 + d4],
                       &gk[(size_t)(bb_ * Tq + t0 + r) * Cq + h * HDq + d4]);
        }
        stage(0, 0);
    }

    float o[4][4];
    float dp[4][2];
#pragma unroll
    for (int im = 0; im < 4; im++) {
#pragma unroll
        for (int e = 0; e < 4; e++) o[im][e] = 0.f;
        dp[im][0] = 0.f; dp[im][1] = 0.f;
    }

    for (int c = 0; c < nch; c++) {
        const int buf = c & 1;
        if (c + 1 < nch) {
            stage(c + 1, (c + 1) & 1);
            asm volatile("cp.async.wait_group 1;" ::: "memory");
        } else {
            asm volatile("cp.async.wait_group 0;" ::: "memory");
        }
        __syncthreads();

        const float* w2c = w2s + buf * 64 * W2S;
        float d[4][2][4];
#pragma unroll
        for (int im = 0; im < 4; im++)
#pragma unroll
            for (int in = 0; in < 2; in++)
#pragma unroll
                for (int e = 0; e < 4; e++) d[im][in][e] = 0.f;

#pragma unroll
        for (int kf = 0; kf < 8; kf++) {
            unsigned a0[4], a1[4], a2[4], a3[4];
#pragma unroll
            for (int im = 0; im < 4; im++) {
                int r = im * 16 + g;
                a0[im] = __float_as_uint(ks[r * KSP2 + kf * 8 + tg]);
                a1[im] = __float_as_uint(ks[(r + 8) * KSP2 + kf * 8 + tg]);
                a2[im] = __float_as_uint(ks[r * KSP2 + kf * 8 + tg + 4]);
                a3[im] = __float_as_uint(ks[(r + 8) * KSP2 + kf * 8 + tg + 4]);
            }
#pragma unroll
            for (int in = 0; in < 2; in++) {
                int cc = wid * 16 + in * 8 + g;
                unsigned b0 = __float_as_uint(w2c[(kf * 8 + tg) * W2S + cc]);
                unsigned b1 = __float_as_uint(w2c[(kf * 8 + tg + 4) * W2S + cc]);
#pragma unroll
                for (int im = 0; im < 4; im++)
                    mma_tf32(d[im][in][0], d[im][in][1], d[im][in][2], d[im][in][3],
                             a0[im], a1[im], a2[im], a3[im], b0, b1);
            }
        }

        const int cbase = (c << 7) + wid * 16;
#pragma unroll
        for (int in = 0; in < 2; in++) {
            const int colb = cbase + in * 8 + 2 * tg;
            float2 bz = *(const float2*)&b2[colb];
#pragma unroll
            for (int im = 0; im < 4; im++) {
                const int r1 = t0 + im * 16 + g;
                const int r2 = r1 + 8;
                float s0 = d[im][in][0] + bz.x;
                float s1 = d[im][in][1] + bz.y;
                float s2 = d[im][in][2] + bz.x;
                float s3 = d[im][in][3] + bz.y;
                float e0 = (colb     <= r1) ? __expf(s0) : 0.f;
                float e1 = (colb + 1 <= r1) ? __expf(s1) : 0.f;
                float e2 = (colb     <= r2) ? __expf(s2) : 0.f;
                float e3 = (colb + 1 <= r2) ? __expf(s3) : 0.f;
                dp[im][0] += e0 + e1;
                dp[im][1] += e2 + e3;
                float2 p0, p1;
                p0.x = __uint_as_float(f2tf32(e0));
                p0.y = __uint_as_float(f2tf32(e1));
                p1.x = __uint_as_float(f2tf32(e2));
                p1.y = __uint_as_float(f2tf32(e3));
                int loc = wid * 16 + in * 8 + 2 * tg;
                *(float2*)&ps[(im * 16 + g) * PSS + loc] = p0;
                *(float2*)&ps[(im * 16 + 8 + g) * PSS + loc] = p1;
            }
        }
        __syncthreads();

        const float* vc = vs + buf * 128 * VSS;
#pragma unroll 4
        for (int kf = 0; kf < 16; kf++) {
            const int l0 = kf * 8;
            unsigned b0 = __float_as_uint(vc[(l0 + tg) * VSS + wid * 8 + g]);
            unsigned b1 = __float_as_uint(vc[(l0 + tg + 4) * VSS + wid * 8 + g]);
#pragma unroll
            for (int im = 0; im < 4; im++) {
                int r = im * 16 + g;
                unsigned a0 = __float_as_uint(ps[r * PSS + l0 + tg]);
                unsigned a1 = __float_as_uint(ps[(r + 8) * PSS + l0 + tg]);
                unsigned a2 = __float_as_uint(ps[r * PSS + l0 + tg + 4]);
                unsigned a3 = __float_as_uint(ps[(r + 8) * PSS + l0 + tg + 4]);
                mma_tf32(o[im][0], o[im][1], o[im][2], o[im][3],
                         a0, a1, a2, a3, b0, b1);
            }
        }
        __syncthreads();
    }

#pragma unroll
    for (int im = 0; im < 4; im++) {
#pragma unroll
        for (int hf = 0; hf < 2; hf++) {
            float v = dp[im][hf];
            v += __shfl_xor_sync(0xffffffffu, v, 1);
            v += __shfl_xor_sync(0xffffffffu, v, 2);
            dp[im][hf] = v;
        }
    }
    if (tg == 0) {
#pragma unroll
        for (int im = 0; im < 4; im++) {
            dpart[wid * 64 + im * 16 + g]     = dp[im][0];
            dpart[wid * 64 + im * 16 + 8 + g] = dp[im][1];
        }
    }
    __syncthreads();
    if (tid < 64) {
        float s = 0.f;
#pragma unroll
        for (int w = 0; w < 8; w++) s += dpart[w * 64 + tid];
        denom[tid] = 1.f / s;
    }
    __syncthreads();

    // ---- output: write y directly as bf16 hi/lo planes ----
#pragma unroll
    for (int im = 0; im < 4; im++) {
        const int r = im * 16 + g;
        const float iv1 = denom[r];
        const float iv2 = denom[r + 8];
        float y0 = o[im][0] * iv1, y1 = o[im][1] * iv1;
        float y2 = o[im][2] * iv2, y3 = o[im][3] * iv2;
        __nv_bfloat16 h0, l0, h1, l1, h2, l2, h3, l3;
        bf16_split(y0, h0, l0); bf16_split(y1, h1, l1);
        bf16_split(y2, h2, l2); bf16_split(y3, h3, l3);
        size_t off1 = (size_t)(bb_ * Tq + t0 + r) * Cq + h * HDq + wid * 8 + 2 * tg;
        size_t off2 = (size_t)(bb_ * Tq + t0 + r + 8) * Cq + h * HDq + wid * 8 + 2 * tg;
        __nv_bfloat162 ph0; ph0.x = h0; ph0.y = h1;
        __nv_bfloat162 pl0; pl0.x = l0; pl0.y = l1;
        __nv_bfloat162 ph1; ph1.x = h2; ph1.y = h3;
        __nv_bfloat162 pl1; pl1.x = l2; pl1.y = l3;
        *(__nv_bfloat162*)&yhi[off1] = ph0;
        *(__nv_bfloat162*)&ylo[off1] = pl0;
        *(__nv_bfloat162*)&yhi[off2] = ph1;
        *(__nv_bfloat162*)&ylo[off2] = pl1;
    }
}

// ---------------------------------------------------------------------------
extern "C" void kernel_launch(void* const* d_in, const int* in_sizes, int n_in,
                              void* d_out, int out_size)
{
    const float* x       = (const float*)d_in[0];
    const float* w1_w    = (const float*)d_in[1];
    const float* w1_b    = (const float*)d_in[2];
    const float* w2      = (const float*)d_in[3];
    const float* b2      = (const float*)d_in[4];
    const float* value_w = (const float*)d_in[5];
    const float* value_b = (const float*)d_in[6];
    const float* proj_w  = (const float*)d_in[7];
    const float* proj_b  = (const float*)d_in[8];
    float* out = (float*)d_out;

    float *pk, *pv, *pw2r;
    __nv_bfloat16 *pahi, *palo, *pwhi, *pwlo;
    cudaGetSymbolAddress((void**)&pk,   g_k);
    cudaGetSymbolAddress((void**)&pv,   g_v);
    cudaGetSymbolAddress((void**)&pw2r, g_w2r);
    cudaGetSymbolAddress((void**)&pahi, g_ahi);
    cudaGetSymbolAddress((void**)&palo, g_alo);
    cudaGetSymbolAddress((void**)&pwhi, g_whi);
    cudaGetSymbolAddress((void**)&pwlo, g_wlo);

    const int SMEM_GEMM = 8 * PLW * (int)sizeof(unsigned);            // 80 KB
    const int SMEM_ATTN = (64 * KSP2 + 2 * 64 * W2S + 2 * 128 * VSS +
                           64 * PSS + 8 * 64 + 64) * (int)sizeof(float);
    cudaFuncSetAttribute(gemm_bf16_kernel<true, true>,
                         cudaFuncAttributeMaxDynamicSharedMemorySize, SMEM_GEMM);
    cudaFuncSetAttribute(gemm_bf16_kernel<false, true>,
                         cudaFuncAttributeMaxDynamicSharedMemorySize, SMEM_GEMM);
    cudaFuncSetAttribute(gemm_bf16_kernel<false, false>,
                         cudaFuncAttributeMaxDynamicSharedMemorySize, SMEM_GEMM);
    cudaFuncSetAttribute(attn2_kernel,
                         cudaFuncAttributeMaxDynamicSharedMemorySize, SMEM_ATTN);

    const int Mrows = Bq * Tq;                 // 4096
    const int NACT4 = Mrows * Cq / 4;
    const int NW4   = Cq * Cq / 4;
    const int NW24  = Hq * HDq * Mq / 4;
    dim3 gemm_grid(Cq / 128, Mrows / 128);     // (8, 32)

    // prep: split x (bf16 hi/lo), round w2 (tf32)
    split_bf16_kernel<<<(NACT4 + 255) / 256, 256>>>(
        (const float4*)x, (__nv_bfloat162*)pahi, (__nv_bfloat162*)palo, NACT4);
    round_kernel<<<(NW24 + 255) / 256, 256>>>(
        (const float4*)w2, (float4*)pw2r, NW24);

    // k = relu(x @ w1^T + b1), tf32-rounded output
    split_bf16_kernel<<<(NW4 + 255) / 256, 256>>>(
        (const float4*)w1_w, (__nv_bfloat162*)pwhi, (__nv_bfloat162*)pwlo, NW4);
    gemm_bf16_kernel<true, true><<<gemm_grid, 256, SMEM_GEMM>>>(
        pahi, palo, pwhi, pwlo, w1_b, pk, Mrows, Cq, Cq);

    // v = x @ value^T + vb, tf32-rounded output
    split_bf16_kernel<<<(NW4 + 255) / 256, 256>>>(
        (const float4*)value_w, (__nv_bfloat162*)pwhi, (__nv_bfloat162*)pwlo, NW4);
    gemm_bf16_kernel<false, true><<<gemm_grid, 256, SMEM_GEMM>>>(
        pahi, palo, pwhi, pwlo, value_b, pv, Mrows, Cq, Cq);

    // attention: writes y bf16 hi/lo planes (overwrites x planes)
    dim3 agrid(Tq / BMq, Hq, Bq);              // (32, 16, 2)
    attn2_kernel<<<agrid, 256, SMEM_ATTN>>>(pk, pv, pw2r, b2, pahi, palo);

    // out = y @ proj^T + pb (fp32 output)
    split_bf16_kernel<<<(NW4 + 255) / 256, 256>>>(
        (const float4*)proj_w, (__nv_bfloat162*)pwhi, (__nv_bfloat162*)pwlo, NW4);
    gemm_bf16_kernel<false, false><<<gemm_grid, 256, SMEM_GEMM>>>(
        pahi, palo, pwhi, pwlo, proj_b, out, Mrows, Cq, Cq);
}

// round 9
// speedup vs baseline: 8.3763x; 1.1036x over previous
#include <cuda_runtime.h>
#include <cuda_bf16.h>
#include <math.h>

// Problem constants
#define Bq   2
#define Tq   2048
#define Cq   1024
#define Hq   16
#define HDq  64
#define Mq   2048

// Scratch (allocation-free rule: __device__ globals)
__device__ float         g_k[Bq * Tq * Cq];    // relu(x@w1^T+b1), tf32-rounded
__device__ float         g_v[Bq * Tq * Cq];    // x@value^T+vb, tf32-rounded
__device__ __nv_bfloat16 g_ahi[Bq * Tq * Cq];  // activation hi plane (x, then y)
__device__ __nv_bfloat16 g_alo[Bq * Tq * Cq];  // activation lo plane
__device__ __nv_bfloat16 g_whi[Cq * Cq];       // weight hi plane (per-GEMM reuse)
__device__ __nv_bfloat16 g_wlo[Cq * Cq];       // weight lo plane
__device__ float         g_w2r[Hq * HDq * Mq]; // w2 tf32-rounded

// ---------------------------------------------------------------------------
// helpers
// ---------------------------------------------------------------------------
__device__ __forceinline__ unsigned f2tf32(float x) {
    unsigned u;
    asm("cvt.rna.tf32.f32 %0, %1;" : "=r"(u) : "f"(x));
    return u;
}

__device__ __forceinline__ void mma_tf32(
    float& d0, float& d1, float& d2, float& d3,
    unsigned a0, unsigned a1, unsigned a2, unsigned a3,
    unsigned b0, unsigned b1)
{
    asm volatile(
        "mma.sync.aligned.m16n8k8.row.col.f32.tf32.tf32.f32 "
        "{%0,%1,%2,%3}, {%4,%5,%6,%7}, {%8,%9}, {%0,%1,%2,%3};"
        : "+f"(d0), "+f"(d1), "+f"(d2), "+f"(d3)
        : "r"(a0), "r"(a1), "r"(a2), "r"(a3), "r"(b0), "r"(b1));
}

__device__ __forceinline__ void mma_bf16(
    float& d0, float& d1, float& d2, float& d3,
    unsigned a0, unsigned a1, unsigned a2, unsigned a3,
    unsigned b0, unsigned b1)
{
    asm volatile(
        "mma.sync.aligned.m16n8k16.row.col.f32.bf16.bf16.f32 "
        "{%0,%1,%2,%3}, {%4,%5,%6,%7}, {%8,%9}, {%0,%1,%2,%3};"
        : "+f"(d0), "+f"(d1), "+f"(d2), "+f"(d3)
        : "r"(a0), "r"(a1), "r"(a2), "r"(a3), "r"(b0), "r"(b1));
}

__device__ __forceinline__ void cp_async16(void* s, const void* g) {
    unsigned sa = (unsigned)__cvta_generic_to_shared(s);
    asm volatile("cp.async.cg.shared.global [%0], [%1], 16;" :: "r"(sa), "l"(g));
}

__device__ __forceinline__ void bf16_split(float v, __nv_bfloat16& h, __nv_bfloat16& l) {
    h = __float2bfloat16_rn(v);
    l = __float2bfloat16_rn(v - __bfloat162float(h));
}

// ---------------------------------------------------------------------------
// Prep kernels
// ---------------------------------------------------------------------------
__global__ __launch_bounds__(256) void split_bf16_kernel(
    const float4* __restrict__ in, __nv_bfloat162* __restrict__ hi,
    __nv_bfloat162* __restrict__ lo, int n4)
{
    int i = blockIdx.x * 256 + threadIdx.x;
    if (i < n4) {
        float4 v = in[i];
        __nv_bfloat16 hx, lx, hy, ly, hz, lz, hw, lw;
        bf16_split(v.x, hx, lx);
        bf16_split(v.y, hy, ly);
        bf16_split(v.z, hz, lz);
        bf16_split(v.w, hw, lw);
        __nv_bfloat162 h0; h0.x = hx; h0.y = hy;
        __nv_bfloat162 h1; h1.x = hz; h1.y = hw;
        __nv_bfloat162 l0; l0.x = lx; l0.y = ly;
        __nv_bfloat162 l1; l1.x = lz; l1.y = lw;
        hi[2 * i] = h0; hi[2 * i + 1] = h1;
        lo[2 * i] = l0; lo[2 * i + 1] = l1;
    }
}

__global__ __launch_bounds__(256) void round_kernel(
    const float4* __restrict__ in, float4* __restrict__ out, int n4)
{
    int i = blockIdx.x * 256 + threadIdx.x;
    if (i < n4) {
        float4 v = in[i];
        float4 o;
        o.x = __uint_as_float(f2tf32(v.x));
        o.y = __uint_as_float(f2tf32(v.y));
        o.z = __uint_as_float(f2tf32(v.z));
        o.w = __uint_as_float(f2tf32(v.w));
        out[i] = o;
    }
}

// ---------------------------------------------------------------------------
// Dense GEMM via 3x bf16 hi/lo mma, cp.async 2-stage, 2 CTAs/SM:
//   C[M,N] = act(A[M,K] @ W[N,K]^T + bias[N])
// Block 128x128, K-tile 32 elts, 8 warps (4m x 2n). B-fragments loaded
// per-n-tile to keep live regs under the 128 cap for 2 CTAs/SM.
// ---------------------------------------------------------------------------
#define ST   20
#define PLW  2560   // 128 * ST words per plane-stage

template <bool RELU, bool ROUND_OUT>
__global__ __launch_bounds__(256, 2) void gemm_bf16_kernel(
    const __nv_bfloat16* __restrict__ Ahi, const __nv_bfloat16* __restrict__ Alo,
    const __nv_bfloat16* __restrict__ Whi, const __nv_bfloat16* __restrict__ Wlo,
    const float* __restrict__ bias, float* __restrict__ Cmat,
    int Mdim, int Ndim, int Kdim)
{
    extern __shared__ unsigned smu[];
    unsigned* sAh = smu;
    unsigned* sAl = sAh + 2 * PLW;
    unsigned* sBh = sAl + 2 * PLW;
    unsigned* sBl = sBh + 2 * PLW;

    const int tid  = threadIdx.x;
    const int lane = tid & 31;
    const int wid  = tid >> 5;
    const int wm   = (wid & 3) * 32;
    const int wn   = (wid >> 2) * 64;
    const int g    = lane >> 2;
    const int tg   = lane & 3;

    const int m0 = blockIdx.y * 128;
    const int n0 = blockIdx.x * 128;
    const int NK = Kdim >> 5;          // k32 tiles

    float acc[2][8][4];
#pragma unroll
    for (int im = 0; im < 2; im++)
#pragma unroll
        for (int in = 0; in < 8; in++)
#pragma unroll
            for (int e = 0; e < 4; e++) acc[im][in][e] = 0.f;

    auto load_stage = [&](int kt, int st) {
        const int k0 = kt << 5;
#pragma unroll
        for (int i = 0; i < 8; i++) {
            int cc = tid + (i & 1) * 256;   // 0..511
            int r  = cc >> 2;               // 0..127
            int j  = cc & 3;                // 16B chunk = 8 elts = 4 words
            if ((i >> 1) == 0)
                cp_async16(&sAh[st * PLW + r * ST + 4 * j],
                           &Ahi[(size_t)(m0 + r) * Kdim + k0 + 8 * j]);
            else if ((i >> 1) == 1)
                cp_async16(&sAl[st * PLW + r * ST + 4 * j],
                           &Alo[(size_t)(m0 + r) * Kdim + k0 + 8 * j]);
            else if ((i >> 1) == 2)
                cp_async16(&sBh[st * PLW + r * ST + 4 * j],
                           &Whi[(size_t)(n0 + r) * Kdim + k0 + 8 * j]);
            else
                cp_async16(&sBl[st * PLW + r * ST + 4 * j],
                           &Wlo[(size_t)(n0 + r) * Kdim + k0 + 8 * j]);
        }
        asm volatile("cp.async.commit_group;" ::: "memory");
    };

    load_stage(0, 0);

    for (int kt = 0; kt < NK; kt++) {
        const int cur = kt & 1;
        if (kt + 1 < NK) {
            load_stage(kt + 1, (kt + 1) & 1);
            asm volatile("cp.async.wait_group 1;" ::: "memory");
        } else {
            asm volatile("cp.async.wait_group 0;" ::: "memory");
        }
        __syncthreads();

        const unsigned* pAh = sAh + cur * PLW;
        const unsigned* pAl = sAl + cur * PLW;
        const unsigned* pBh = sBh + cur * PLW;
        const unsigned* pBl = sBl + cur * PLW;

#pragma unroll
        for (int kw = 0; kw < 16; kw += 8) {   // two k16 steps per tile
            unsigned ah[2][4], al[2][4];
#pragma unroll
            for (int im = 0; im < 2; im++) {
                int r = wm + im * 16 + g;
                ah[im][0] = pAh[r * ST + kw + tg];
                ah[im][1] = pAh[(r + 8) * ST + kw + tg];
                ah[im][2] = pAh[r * ST + kw + tg + 4];
                ah[im][3] = pAh[(r + 8) * ST + kw + tg + 4];
                al[im][0] = pAl[r * ST + kw + tg];
                al[im][1] = pAl[(r + 8) * ST + kw + tg];
                al[im][2] = pAl[r * ST + kw + tg + 4];
                al[im][3] = pAl[(r + 8) * ST + kw + tg + 4];
            }
#pragma unroll
            for (int in = 0; in < 8; in++) {
                int c = wn + in * 8 + g;
                unsigned bh0 = pBh[c * ST + kw + tg];
                unsigned bh1 = pBh[c * ST + kw + tg + 4];
                unsigned bl0 = pBl[c * ST + kw + tg];
                unsigned bl1 = pBl[c * ST + kw + tg + 4];
#pragma unroll
                for (int im = 0; im < 2; im++) {
                    float* d = acc[im][in];
                    mma_bf16(d[0], d[1], d[2], d[3],
                             ah[im][0], ah[im][1], ah[im][2], ah[im][3],
                             bh0, bh1);
                    mma_bf16(d[0], d[1], d[2], d[3],
                             ah[im][0], ah[im][1], ah[im][2], ah[im][3],
                             bl0, bl1);
                    mma_bf16(d[0], d[1], d[2], d[3],
                             al[im][0], al[im][1], al[im][2], al[im][3],
                             bh0, bh1);
                }
            }
        }
        __syncthreads();
    }

#pragma unroll
    for (int in = 0; in < 8; in++) {
        int col = n0 + wn + in * 8 + 2 * tg;
        float2 bz = *(const float2*)&bias[col];
#pragma unroll
        for (int im = 0; im < 2; im++) {
            int row = m0 + wm + im * 16 + g;
            float v0 = acc[im][in][0] + bz.x;
            float v1 = acc[im][in][1] + bz.y;
            float v2 = acc[im][in][2] + bz.x;
            float v3 = acc[im][in][3] + bz.y;
            if (RELU) {
                v0 = fmaxf(v0, 0.f); v1 = fmaxf(v1, 0.f);
                v2 = fmaxf(v2, 0.f); v3 = fmaxf(v3, 0.f);
            }
            if (ROUND_OUT) {
                v0 = __uint_as_float(f2tf32(v0));
                v1 = __uint_as_float(f2tf32(v1));
                v2 = __uint_as_float(f2tf32(v2));
                v3 = __uint_as_float(f2tf32(v3));
            }
            float2 p0; p0.x = v0; p0.y = v1;
            float2 p1; p1.x = v2; p1.y = v3;
            *(float2*)&Cmat[(size_t)row * Ndim + col] = p0;
            *(float2*)&Cmat[(size_t)(row + 8) * Ndim + col] = p1;
        }
    }
}

// ---------------------------------------------------------------------------
// Chunked fused attention v3: block = (b, h, 64 q rows), 64-col chunks,
// ~111 KB smem -> 2 CTAs/SM. Same math as R7/R8 (tf32 mma, no max-pass).
// ---------------------------------------------------------------------------
#define BMq  64
#define BCq  64
#define KSP2 68
#define W2S  72
#define VSS  72
#define PSS  68

__global__ __launch_bounds__(256, 2) void attn2_kernel(
    const float* __restrict__ gk, const float* __restrict__ gv,
    const float* __restrict__ w2r, const float* __restrict__ b2,
    __nv_bfloat16* __restrict__ yhi, __nv_bfloat16* __restrict__ ylo)
{
    extern __shared__ float sm[];
    float* ks    = sm;                         // [64][68]
    float* w2s   = ks + 64 * KSP2;             // [2][64][72]
    float* vs    = w2s + 2 * 64 * W2S;         // [2][64][72]
    float* ps    = vs + 2 * 64 * VSS;          // [64][68]
    float* dpart = ps + 64 * PSS;              // [8][64]
    float* denom = dpart + 8 * 64;             // [64]

    const int t0  = blockIdx.x * BMq;
    const int h   = blockIdx.y;
    const int bb_ = blockIdx.z;
    const int tid = threadIdx.x;
    const int lane = tid & 31;
    const int wid  = tid >> 5;
    const int g    = lane >> 2;
    const int tg   = lane & 3;

    const int nch = (t0 >> 6) + 1;             // ceil((t0+64)/64)

    auto stage = [&](int c, int buf) {
        const int c0 = c << 6;
        float* w2d = w2s + buf * 64 * W2S;
        float* vsd = vs + buf * 64 * VSS;
        const float* w2g = w2r + (size_t)h * HDq * Mq + c0;
        const float* vg  = gv + (size_t)bb_ * Tq * Cq + (size_t)c0 * Cq + h * HDq;
#pragma unroll
        for (int i = 0; i < 4; i++) {           // w2: 64x64 = 1024 16B chunks
            int cc = tid + i * 256;
            int d  = cc >> 4;
            int m4 = (cc & 15) << 2;
            cp_async16(&w2d[d * W2S + m4], &w2g[(size_t)d * Mq + m4]);
        }
#pragma unroll
        for (int i = 0; i < 4; i++) {           // V: 64x64 = 1024 16B chunks
            int cc = tid + i * 256;
            int l  = cc >> 4;
            int d4 = (cc & 15) << 2;
            cp_async16(&vsd[l * VSS + d4], &vg[(size_t)l * Cq + d4]);
        }
        asm volatile("cp.async.commit_group;" ::: "memory");
    };

    {
#pragma unroll
        for (int i = 0; i < 4; i++) {           // K: 64x64
            int cc = tid + i * 256;
            int r  = cc >> 4;
            int d4 = (cc & 15) << 2;
            cp_async16(&ks[r * KSP2 + d4],
                       &gk[(size_t)(bb_ * Tq + t0 + r) * Cq + h * HDq + d4]);
        }
        stage(0, 0);
    }

    float o[4][4];      // PV accumulators: warp cols [wid*8, wid*8+8)
    float dp[4][2];     // denom partials (im, row-half)
#pragma unroll
    for (int im = 0; im < 4; im++) {
#pragma unroll
        for (int e = 0; e < 4; e++) o[im][e] = 0.f;
        dp[im][0] = 0.f; dp[im][1] = 0.f;
    }

    for (int c = 0; c < nch; c++) {
        const int buf = c & 1;
        if (c + 1 < nch) {
            stage(c + 1, (c + 1) & 1);
            asm volatile("cp.async.wait_group 1;" ::: "memory");
        } else {
            asm volatile("cp.async.wait_group 0;" ::: "memory");
        }
        __syncthreads();

        // ---- score mma: warp owns chunk cols [wid*8, wid*8+8) ----
        const float* w2c = w2s + buf * 64 * W2S;
        float d[4][4];
#pragma unroll
        for (int im = 0; im < 4; im++)
#pragma unroll
            for (int e = 0; e < 4; e++) d[im][e] = 0.f;

#pragma unroll
        for (int kf = 0; kf < 8; kf++) {
            const int cc = wid * 8 + g;
            unsigned b0 = __float_as_uint(w2c[(kf * 8 + tg) * W2S + cc]);
            unsigned b1 = __float_as_uint(w2c[(kf * 8 + tg + 4) * W2S + cc]);
#pragma unroll
            for (int im = 0; im < 4; im++) {
                int r = im * 16 + g;
                unsigned a0 = __float_as_uint(ks[r * KSP2 + kf * 8 + tg]);
                unsigned a1 = __float_as_uint(ks[(r + 8) * KSP2 + kf * 8 + tg]);
                unsigned a2 = __float_as_uint(ks[r * KSP2 + kf * 8 + tg + 4]);
                unsigned a3 = __float_as_uint(ks[(r + 8) * KSP2 + kf * 8 + tg + 4]);
                mma_tf32(d[im][0], d[im][1], d[im][2], d[im][3],
                         a0, a1, a2, a3, b0, b1);
            }
        }

        // ---- bias + exp + causal mask + ps store + denom partials ----
        {
            const int colb = (c << 6) + wid * 8 + 2 * tg;
            float2 bz = *(const float2*)&b2[colb];
            const int loc = wid * 8 + 2 * tg;
#pragma unroll
            for (int im = 0; im < 4; im++) {
                const int r1 = t0 + im * 16 + g;
                const int r2 = r1 + 8;
                float s0 = d[im][0] + bz.x;
                float s1 = d[im][1] + bz.y;
                float s2 = d[im][2] + bz.x;
                float s3 = d[im][3] + bz.y;
                float e0 = (colb     <= r1) ? __expf(s0) : 0.f;
                float e1 = (colb + 1 <= r1) ? __expf(s1) : 0.f;
                float e2 = (colb     <= r2) ? __expf(s2) : 0.f;
                float e3 = (colb + 1 <= r2) ? __expf(s3) : 0.f;
                dp[im][0] += e0 + e1;
                dp[im][1] += e2 + e3;
                float2 p0, p1;
                p0.x = __uint_as_float(f2tf32(e0));
                p0.y = __uint_as_float(f2tf32(e1));
                p1.x = __uint_as_float(f2tf32(e2));
                p1.y = __uint_as_float(f2tf32(e3));
                *(float2*)&ps[(im * 16 + g) * PSS + loc] = p0;
                *(float2*)&ps[(im * 16 + 8 + g) * PSS + loc] = p1;
            }
        }
        __syncthreads();

        // ---- PV mma: warp owns out cols [wid*8, wid*8+8) ----
        const float* vc = vs + buf * 64 * VSS;
#pragma unroll
        for (int kf = 0; kf < 8; kf++) {
            const int l0 = kf * 8;
            unsigned b0 = __float_as_uint(vc[(l0 + tg) * VSS + wid * 8 + g]);
            unsigned b1 = __float_as_uint(vc[(l0 + tg + 4) * VSS + wid * 8 + g]);
#pragma unroll
            for (int im = 0; im < 4; im++) {
                int r = im * 16 + g;
                unsigned a0 = __float_as_uint(ps[r * PSS + l0 + tg]);
                unsigned a1 = __float_as_uint(ps[(r + 8) * PSS + l0 + tg]);
                unsigned a2 = __float_as_uint(ps[r * PSS + l0 + tg + 4]);
                unsigned a3 = __float_as_uint(ps[(r + 8) * PSS + l0 + tg + 4]);
                mma_tf32(o[im][0], o[im][1], o[im][2], o[im][3],
                         a0, a1, a2, a3, b0, b1);
            }
        }
        __syncthreads();
    }

    // ---- denominator reduction ----
#pragma unroll
    for (int im = 0; im < 4; im++) {
#pragma unroll
        for (int hf = 0; hf < 2; hf++) {
            float v = dp[im][hf];
            v += __shfl_xor_sync(0xffffffffu, v, 1);
            v += __shfl_xor_sync(0xffffffffu, v, 2);
            dp[im][hf] = v;
        }
    }
    if (tg == 0) {
#pragma unroll
        for (int im = 0; im < 4; im++) {
            dpart[wid * 64 + im * 16 + g]     = dp[im][0];
            dpart[wid * 64 + im * 16 + 8 + g] = dp[im][1];
        }
    }
    __syncthreads();
    if (tid < 64) {
        float s = 0.f;
#pragma unroll
        for (int w = 0; w < 8; w++) s += dpart[w * 64 + tid];
        denom[tid] = 1.f / s;
    }
    __syncthreads();

    // ---- output: write y directly as bf16 hi/lo planes ----
#pragma unroll
    for (int im = 0; im < 4; im++) {
        const int r = im * 16 + g;
        const float iv1 = denom[r];
        const float iv2 = denom[r + 8];
        float y0 = o[im][0] * iv1, y1 = o[im][1] * iv1;
        float y2 = o[im][2] * iv2, y3 = o[im][3] * iv2;
        __nv_bfloat16 h0, l0, h1, l1, h2, l2, h3, l3;
        bf16_split(y0, h0, l0); bf16_split(y1, h1, l1);
        bf16_split(y2, h2, l2); bf16_split(y3, h3, l3);
        size_t off1 = (size_t)(bb_ * Tq + t0 + r) * Cq + h * HDq + wid * 8 + 2 * tg;
        size_t off2 = (size_t)(bb_ * Tq + t0 + r + 8) * Cq + h * HDq + wid * 8 + 2 * tg;
        __nv_bfloat162 ph0; ph0.x = h0; ph0.y = h1;
        __nv_bfloat162 pl0; pl0.x = l0; pl0.y = l1;
        __nv_bfloat162 ph1; ph1.x = h2; ph1.y = h3;
        __nv_bfloat162 pl1; pl1.x = l2; pl1.y = l3;
        *(__nv_bfloat162*)&yhi[off1] = ph0;
        *(__nv_bfloat162*)&ylo[off1] = pl0;
        *(__nv_bfloat162*)&yhi[off2] = ph1;
        *(__nv_bfloat162*)&ylo[off2] = pl1;
    }
}

// ---------------------------------------------------------------------------
extern "C" void kernel_launch(void* const* d_in, const int* in_sizes, int n_in,
                              void* d_out, int out_size)
{
    const float* x       = (const float*)d_in[0];
    const float* w1_w    = (const float*)d_in[1];
    const float* w1_b    = (const float*)d_in[2];
    const float* w2      = (const float*)d_in[3];
    const float* b2      = (const float*)d_in[4];
    const float* value_w = (const float*)d_in[5];
    const float* value_b = (const float*)d_in[6];
    const float* proj_w  = (const float*)d_in[7];
    const float* proj_b  = (const float*)d_in[8];
    float* out = (float*)d_out;

    float *pk, *pv, *pw2r;
    __nv_bfloat16 *pahi, *palo, *pwhi, *pwlo;
    cudaGetSymbolAddress((void**)&pk,   g_k);
    cudaGetSymbolAddress((void**)&pv,   g_v);
    cudaGetSymbolAddress((void**)&pw2r, g_w2r);
    cudaGetSymbolAddress((void**)&pahi, g_ahi);
    cudaGetSymbolAddress((void**)&palo, g_alo);
    cudaGetSymbolAddress((void**)&pwhi, g_whi);
    cudaGetSymbolAddress((void**)&pwlo, g_wlo);

    const int SMEM_GEMM = 8 * PLW * (int)sizeof(unsigned);            // 80 KB
    const int SMEM_ATTN = (64 * KSP2 + 2 * 64 * W2S + 2 * 64 * VSS +
                           64 * PSS + 8 * 64 + 64) * (int)sizeof(float); // ~111 KB
    cudaFuncSetAttribute(gemm_bf16_kernel<true, true>,
                         cudaFuncAttributeMaxDynamicSharedMemorySize, SMEM_GEMM);
    cudaFuncSetAttribute(gemm_bf16_kernel<false, true>,
                         cudaFuncAttributeMaxDynamicSharedMemorySize, SMEM_GEMM);
    cudaFuncSetAttribute(gemm_bf16_kernel<false, false>,
                         cudaFuncAttributeMaxDynamicSharedMemorySize, SMEM_GEMM);
    cudaFuncSetAttribute(attn2_kernel,
                         cudaFuncAttributeMaxDynamicSharedMemorySize, SMEM_ATTN);

    const int Mrows = Bq * Tq;                 // 4096
    const int NACT4 = Mrows * Cq / 4;
    const int NW4   = Cq * Cq / 4;
    const int NW24  = Hq * HDq * Mq / 4;
    dim3 gemm_grid(Cq / 128, Mrows / 128);     // (8, 32)

    // prep: split x (bf16 hi/lo), round w2 (tf32)
    split_bf16_kernel<<<(NACT4 + 255) / 256, 256>>>(
        (const float4*)x, (__nv_bfloat162*)pahi, (__nv_bfloat162*)palo, NACT4);
    round_kernel<<<(NW24 + 255) / 256, 256>>>(
        (const float4*)w2, (float4*)pw2r, NW24);

    // k = relu(x @ w1^T + b1), tf32-rounded output
    split_bf16_kernel<<<(NW4 + 255) / 256, 256>>>(
        (const float4*)w1_w, (__nv_bfloat162*)pwhi, (__nv_bfloat162*)pwlo, NW4);
    gemm_bf16_kernel<true, true><<<gemm_grid, 256, SMEM_GEMM>>>(
        pahi, palo, pwhi, pwlo, w1_b, pk, Mrows, Cq, Cq);

    // v = x @ value^T + vb, tf32-rounded output
    split_bf16_kernel<<<(NW4 + 255) / 256, 256>>>(
        (const float4*)value_w, (__nv_bfloat162*)pwhi, (__nv_bfloat162*)pwlo, NW4);
    gemm_bf16_kernel<false, true><<<gemm_grid, 256, SMEM_GEMM>>>(
        pahi, palo, pwhi, pwlo, value_b, pv, Mrows, Cq, Cq);

    // attention: writes y bf16 hi/lo planes (overwrites x planes)
    dim3 agrid(Tq / BMq, Hq, Bq);              // (32, 16, 2)
    attn2_kernel<<<agrid, 256, SMEM_ATTN>>>(pk, pv, pw2r, b2, pahi, palo);

    // out = y @ proj^T + pb (fp32 output)
    split_bf16_kernel<<<(NW4 + 255) / 256, 256>>>(
        (const float4*)proj_w, (__nv_bfloat162*)pwhi, (__nv_bfloat162*)pwlo, NW4);
    gemm_bf16_kernel<false, false><<<gemm_grid, 256, SMEM_GEMM>>>(
        pahi, palo, pwhi, pwlo, proj_b, out, Mrows, Cq, Cq);
}